// round 11
// baseline (speedup 1.0000x reference)
#include <cuda_runtime.h>
#include <cuda_bf16.h>
#include <cstdint>
#include <cstddef>

// VectorQuantizer on GB300 (sm_103a)
// bf16 HFMA2 coarse scoring (rt=2 fma class) + margin flag + exact fp32 rescore.
// z_e: (16,256,64,64) fp32 ; embedding: (1024,256) fp32

#define NEMB 1024
#define EDIM 256
#define HW   4096
#define NPIX 65536
#define NC   16777216

#define MARGIN  8.0f
#define FLAGCAP 65536

// smem: 3 stages x (A 8KB + B 8KB) + e2 4KB
#define STG    16384
#define SM_E2  (3 * STG)
#define SM_TOT (3 * STG + 4096)

// ---- device scratch ----
__device__ __align__(128) __nv_bfloat16 g_AT[(size_t)EDIM * NPIX];  // [k][pix]
__device__ __align__(128) __nv_bfloat16 g_BT[EDIM * NEMB];          // [k][code]
__device__ __align__(16) float  g_e2[NEMB];
__device__ int    g_idx[NPIX];
__device__ double g_part[2048];
__device__ int    g_nflag;
__device__ int    g_flag[FLAGCAP];

static __device__ __forceinline__ uint32_t s2u(const void* p) {
    uint32_t a;
    asm("{ .reg .u64 t; cvta.to.shared.u64 t, %1; cvt.u32.u64 %0, t; }" : "=r"(a) : "l"(p));
    return a;
}
static __device__ __forceinline__ void cpa16(uint32_t dst, const void* src) {
    asm volatile("cp.async.cg.shared.global [%0], [%1], 16;" :: "r"(dst), "l"(src));
}
static __device__ __forceinline__ uint32_t bffma2(uint32_t a, uint32_t b, uint32_t c) {
    __nv_bfloat162 r = __hfma2(*reinterpret_cast<__nv_bfloat162*>(&a),
                               *reinterpret_cast<__nv_bfloat162*>(&b),
                               *reinterpret_cast<__nv_bfloat162*>(&c));
    return *reinterpret_cast<uint32_t*>(&r);
}

// ============================================================
// K1: per-code squared norms (exact fp32). One warp per code.
// ============================================================
__global__ void k_e2(const float* __restrict__ emb) {
    int warp = (blockIdx.x * blockDim.x + threadIdx.x) >> 5;
    int lane = threadIdx.x & 31;
    if (warp >= NEMB) return;
    const float4* row = reinterpret_cast<const float4*>(emb + (size_t)warp * EDIM);
    float s = 0.f;
    #pragma unroll
    for (int i = lane; i < EDIM / 4; i += 32) {
        float4 v = row[i];
        s += v.x * v.x + v.y * v.y + v.z * v.z + v.w * v.w;
    }
    #pragma unroll
    for (int o = 16; o; o >>= 1) s += __shfl_xor_sync(0xFFFFFFFFu, s, o);
    if (lane == 0) g_e2[warp] = s;
}

// ============================================================
// K2: transpose embedding -> g_BT[k][code] bf16
// ============================================================
__global__ __launch_bounds__(256) void k_bt(const float* __restrict__ emb) {
    __shared__ float tile[32][33];
    const int tx = threadIdx.x & 31;
    const int ty = threadIdx.x >> 5;          // 0..7
    const int c0 = blockIdx.x << 5;           // code tile
    const int k0 = blockIdx.y << 5;           // k tile
    #pragma unroll
    for (int i = 0; i < 4; ++i)
        tile[ty + i * 8][tx] = emb[(size_t)(c0 + ty + i * 8) * EDIM + k0 + tx];
    __syncthreads();
    #pragma unroll
    for (int i = 0; i < 4; ++i)
        g_BT[(size_t)(k0 + ty + i * 8) * NEMB + c0 + tx] =
            __float2bfloat16(tile[tx][ty + i * 8]);
}

// ============================================================
// K3: z_e -> g_AT[k][pix] bf16 (layout-preserving; z is channel-major)
// ============================================================
__global__ __launch_bounds__(256) void k_prep_x(const float* __restrict__ z) {
    if (blockIdx.x == 0 && threadIdx.x == 0) g_nflag = 0;
    const float4* z4 = reinterpret_cast<const float4*>(z);
    int tid = blockIdx.x * blockDim.x + threadIdx.x;
    #pragma unroll
    for (int it = 0; it < 8; ++it) {
        int i = tid + it * 524288;           // float4 index, 4,194,304 total
        float4 v = z4[i];
        int lin = i << 2;
        int hw = lin & 4095;
        int c  = (lin >> 12) & 255;
        int b  = lin >> 20;
        __nv_bfloat162 lo = __float22bfloat162_rn(make_float2(v.x, v.y));
        __nv_bfloat162 hi = __float22bfloat162_rn(make_float2(v.z, v.w));
        uint2 w;
        w.x = *reinterpret_cast<uint32_t*>(&lo);
        w.y = *reinterpret_cast<uint32_t*>(&hi);
        *reinterpret_cast<uint2*>(&g_AT[(size_t)c * NPIX + b * HW + hw]) = w;
    }
}

// ============================================================
// K4: HFMA2 coarse scoring + fused argmin with margin flag.
// CTA = 128 pixels x 1024 codes. 64 steps = 8 cc x 8 kc of 32 k.
// Per step: A [32k][128pix] bf16 8KB + B [32k][128codes] bf16 8KB,
// 3-stage cp.async (R9-proven order). Thread tile 8 pix x 8 codes,
// bf16x2 accumulators (2 codes per reg).
// ============================================================
__global__ __launch_bounds__(256, 2) void k_argmin_bf(void) {
    extern __shared__ char smem[];
    const uint32_t sbase = s2u(smem);
    float* se2 = reinterpret_cast<float*>(smem + SM_E2);

    const int t  = threadIdx.x;
    const int tx = t & 15;             // 8 codes  (tx*8..+7)
    const int ty = t >> 4;             // 8 pixels (ty*8..+7)
    const int pix0 = blockIdx.x << 7;

    #pragma unroll
    for (int i = 0; i < 4; ++i) se2[t + (i << 8)] = g_e2[t + (i << 8)];

    // loader: 1024 granules of 16B per stage (A 0..511, B 512..1023), 4/thread
    // granule g<512 : A kk=g>>4 seg=g&15 ; g>=512: B likewise
    float bv[8], b2[8];
    int   bi[8];
    #pragma unroll
    for (int i = 0; i < 8; ++i) { bv[i] = 3.402823466e38f; b2[i] = 3.402823466e38f; bi[i] = 0; }

    uint32_t acc[8][4];
    #pragma unroll
    for (int i = 0; i < 8; ++i)
        #pragma unroll
        for (int j = 0; j < 4; ++j) acc[i][j] = 0u;

    // ---- prologue: issue steps 0 and 1 ----
    #pragma unroll
    for (int p = 0; p < 2; ++p) {
        const int cc = p >> 3, kc = p & 7;
        const uint32_t ba = sbase + p * STG;
        #pragma unroll
        for (int i = 0; i < 4; ++i) {
            int g = t + (i << 8);
            if (g < 512) {
                int kk = g >> 4, seg = g & 15;
                cpa16(ba + kk * 256 + (seg << 4),
                      &g_AT[(size_t)(kc * 32 + kk) * NPIX + pix0 + (seg << 3)]);
            } else {
                int gb = g - 512, kk = gb >> 4, seg = gb & 15;
                cpa16(ba + 8192 + kk * 256 + (seg << 4),
                      &g_BT[(size_t)(kc * 32 + kk) * NEMB + cc * 128 + (seg << 3)]);
            }
        }
        asm volatile("cp.async.commit_group;" ::: "memory");
    }

    #pragma unroll 1
    for (int g = 0; g < 64; ++g) {
        // 1. own group g complete
        if (g < 63) {
            asm volatile("cp.async.wait_group 1;" ::: "memory");
        } else {
            asm volatile("cp.async.wait_group 0;" ::: "memory");
        }
        // 2. CTA-wide visibility + buffer recycling safe
        __syncthreads();

        // 3. issue group g+2
        if (g + 2 < 64) {
            const int g2 = g + 2;
            const int cc2 = g2 >> 3, kc2 = g2 & 7;
            const uint32_t ba = sbase + (g2 % 3) * STG;
            #pragma unroll
            for (int i = 0; i < 4; ++i) {
                int gg = t + (i << 8);
                if (gg < 512) {
                    int kk = gg >> 4, seg = gg & 15;
                    cpa16(ba + kk * 256 + (seg << 4),
                          &g_AT[(size_t)(kc2 * 32 + kk) * NPIX + pix0 + (seg << 3)]);
                } else {
                    int gb = gg - 512, kk = gb >> 4, seg = gb & 15;
                    cpa16(ba + 8192 + kk * 256 + (seg << 4),
                          &g_BT[(size_t)(kc2 * 32 + kk) * NEMB + cc2 * 128 + (seg << 3)]);
                }
            }
            asm volatile("cp.async.commit_group;" ::: "memory");
        }

        // 4. compute on buffer g%3
        const char* pA = smem + (g % 3) * STG;
        const char* pB = pA + 8192;

        #pragma unroll 8
        for (int kk = 0; kk < 32; ++kk) {
            uint4 av = *reinterpret_cast<const uint4*>(pA + kk * 256 + (ty << 4));
            uint4 bw = *reinterpret_cast<const uint4*>(pB + kk * 256 + (tx << 4));
            uint32_t bb[4] = {bw.x, bw.y, bw.z, bw.w};
            uint32_t ad[8];
            ad[0] = __byte_perm(av.x, av.x, 0x1010);
            ad[1] = __byte_perm(av.x, av.x, 0x3232);
            ad[2] = __byte_perm(av.y, av.y, 0x1010);
            ad[3] = __byte_perm(av.y, av.y, 0x3232);
            ad[4] = __byte_perm(av.z, av.z, 0x1010);
            ad[5] = __byte_perm(av.z, av.z, 0x3232);
            ad[6] = __byte_perm(av.w, av.w, 0x1010);
            ad[7] = __byte_perm(av.w, av.w, 0x3232);
            #pragma unroll
            for (int i = 0; i < 8; ++i)
                #pragma unroll
                for (int j = 0; j < 4; ++j)
                    acc[i][j] = bffma2(ad[i], bb[j], acc[i][j]);
        }

        // ---- epilogue at end of each 128-code chunk (kc == 7) ----
        if ((g & 7) == 7) {
            const int code0 = (g >> 3) << 7;
            #pragma unroll
            for (int i = 0; i < 8; ++i) {
                #pragma unroll
                for (int j = 0; j < 4; ++j) {
                    float2 d = __bfloat1622float2(
                        *reinterpret_cast<__nv_bfloat162*>(&acc[i][j]));
                    acc[i][j] = 0u;
                    int c = code0 + (tx << 3) + 2 * j;
                    float s0 = fmaf(-2.f, d.x, se2[c]);
                    float s1 = fmaf(-2.f, d.y, se2[c + 1]);
                    if (s0 < bv[i]) { b2[i] = bv[i]; bv[i] = s0; bi[i] = c; }
                    else if (s0 < b2[i]) b2[i] = s0;
                    if (s1 < bv[i]) { b2[i] = bv[i]; bv[i] = s1; bi[i] = c + 1; }
                    else if (s1 < b2[i]) b2[i] = s1;
                }
            }
        }
    }

    // ---- cross-thread merge over 16 tx lanes (keep best + 2nd) ----
    #pragma unroll
    for (int o = 8; o; o >>= 1) {
        #pragma unroll
        for (int i = 0; i < 8; ++i) {
            float ov = __shfl_xor_sync(0xFFFFFFFFu, bv[i], o);
            float o2 = __shfl_xor_sync(0xFFFFFFFFu, b2[i], o);
            int   oi = __shfl_xor_sync(0xFFFFFFFFu, bi[i], o);
            if (ov < bv[i] || (ov == bv[i] && oi < bi[i])) {
                b2[i] = fminf(bv[i], o2);
                bv[i] = ov; bi[i] = oi;
            } else {
                b2[i] = fminf(b2[i], ov);
            }
        }
    }
    if (tx == 0) {
        #pragma unroll
        for (int i = 0; i < 8; ++i) {
            int prow = pix0 + (ty << 3) + i;
            g_idx[prow] = bi[i];
            if (b2[i] - bv[i] < MARGIN) {
                int pos = atomicAdd(&g_nflag, 1);
                if (pos < FLAGCAP) g_flag[pos] = prow;
            }
        }
    }
}

// ============================================================
// K5: exact fp32 rescore of margin-flagged pixels (proven)
// ============================================================
__global__ __launch_bounds__(256) void k_fix(const float* __restrict__ z,
                                             const float* __restrict__ emb) {
    __shared__ float sx[8][256];
    const int w = threadIdx.x >> 5, lane = threadIdx.x & 31;
    int n = g_nflag; if (n > FLAGCAP) n = FLAGCAP;
    for (int f = blockIdx.x * 8 + w; f < n; f += gridDim.x * 8) {
        int pix = g_flag[f];
        const float* zb = z + (((size_t)(pix >> 12)) << 20) + (pix & 4095);
        for (int k = lane; k < EDIM; k += 32) sx[w][k] = zb[(size_t)k * HW];
        __syncwarp();
        float bv = 3.402823466e38f; int bi = 0;
        for (int c = lane; c < NEMB; c += 32) {
            const float* e = emb + (size_t)c * EDIM;
            float a0 = 0.f, a1 = 0.f, a2 = 0.f, a3 = 0.f;
            #pragma unroll 8
            for (int k = 0; k < EDIM; k += 4) {
                a0 = fmaf(sx[w][k],     e[k],     a0);
                a1 = fmaf(sx[w][k + 1], e[k + 1], a1);
                a2 = fmaf(sx[w][k + 2], e[k + 2], a2);
                a3 = fmaf(sx[w][k + 3], e[k + 3], a3);
            }
            float sc = g_e2[c] - 2.f * ((a0 + a1) + (a2 + a3));
            if (sc < bv) { bv = sc; bi = c; }
        }
        #pragma unroll
        for (int o = 16; o; o >>= 1) {
            float ov = __shfl_xor_sync(0xFFFFFFFFu, bv, o);
            int   oi = __shfl_xor_sync(0xFFFFFFFFu, bi, o);
            if (ov < bv || (ov == bv && oi < bi)) { bv = ov; bi = oi; }
        }
        if (lane == 0) g_idx[pix] = bi;
        __syncwarp();
    }
}

// ============================================================
// K6: gather z_q, write z_q_st = z_e + (z_q - z_e), loss partials
// ============================================================
__global__ __launch_bounds__(256)
void k_gather(const float* __restrict__ z, const float* __restrict__ emb,
              float* __restrict__ out) {
    __shared__ float sE[32 * 260];
    __shared__ float swarp[8];
    const int t = threadIdx.x;
    const int pix0 = blockIdx.x << 5;

    #pragma unroll
    for (int it = 0; it < 8; ++it) {
        int slot = t + (it << 8);
        int p = slot >> 6, c4 = slot & 63;
        int idx = g_idx[pix0 + p];
        float4 v = *reinterpret_cast<const float4*>(emb + (size_t)idx * EDIM + (c4 << 2));
        *reinterpret_cast<float4*>(&sE[p * 260 + (c4 << 2)]) = v;
    }
    __syncthreads();

    const float* zb = z   + (((size_t)(pix0 >> 12)) << 20) + (pix0 & 4095);
    float*       ob = out + (((size_t)(pix0 >> 12)) << 20) + (pix0 & 4095);

    float lsum = 0.f;
    #pragma unroll
    for (int it = 0; it < 8; ++it) {
        int slot = t + (it << 8);
        int hw = slot & 31, c4 = slot >> 5;
        float4 e = *reinterpret_cast<const float4*>(&sE[hw * 260 + (c4 << 2)]);
        float ev[4] = {e.x, e.y, e.z, e.w};
        #pragma unroll
        for (int j = 0; j < 4; ++j) {
            size_t gg = (size_t)((c4 << 2) + j) * HW + hw;
            float ze = zb[gg];
            float d = ev[j] - ze;
            ob[gg] = ze + d;
            lsum += d * d;
        }
    }
    #pragma unroll
    for (int o = 16; o; o >>= 1) lsum += __shfl_xor_sync(0xFFFFFFFFu, lsum, o);
    if ((t & 31) == 0) swarp[t >> 5] = lsum;
    __syncthreads();
    if (t == 0) {
        double s = 0.0;
        #pragma unroll
        for (int w = 0; w < 8; ++w) s += (double)swarp[w];
        g_part[blockIdx.x] = s;
    }
}

// ============================================================
// K7: loss finalize
// ============================================================
__global__ void k_loss(float* __restrict__ out, int out_size) {
    __shared__ double sd[256];
    int t = threadIdx.x;
    double s = 0.0;
    for (int i = t; i < 2048; i += 256) s += g_part[i];
    sd[t] = s;
    __syncthreads();
    for (int o = 128; o; o >>= 1) {
        if (t < o) sd[t] += sd[t + o];
        __syncthreads();
    }
    if (t == 0 && out_size > NC)
        out[NC] = (float)(0.25 * sd[0] / (double)NC);
}

// ============================================================
extern "C" void kernel_launch(void* const* d_in, const int* in_sizes, int n_in,
                              void* d_out, int out_size) {
    const float* z   = (const float*)d_in[0];
    const float* emb = (const float*)d_in[1];
    float* out = (float*)d_out;

    cudaFuncSetAttribute(k_argmin_bf, cudaFuncAttributeMaxDynamicSharedMemorySize, SM_TOT);

    k_e2     <<<128, 256>>>(emb);
    {
        dim3 grid(32, 8);
        k_bt<<<grid, 256>>>(emb);
    }
    k_prep_x  <<<2048, 256>>>(z);
    k_argmin_bf<<<512, 256, SM_TOT>>>();
    k_fix     <<<256, 256>>>(z, emb);
    k_gather  <<<2048, 256>>>(z, emb, out);
    k_loss    <<<1, 256>>>(out, out_size);
}

// round 12
// speedup vs baseline: 5.7745x; 5.7745x over previous
#include <cuda_runtime.h>
#include <cuda_bf16.h>
#include <cstdint>
#include <cstddef>

// VectorQuantizer on GB300 (sm_103a)
// 1-term bf16 mma.sync scoring (R4-proven loop, fp32 accum) + MARGIN 0.5
// flag + exact fp32 rescore (R7-proven). z_e: (16,256,64,64) fp32 ;
// embedding: (1024,256) fp32

#define NEMB 1024
#define EDIM 256
#define HW   4096
#define NPIX 65536
#define NC   16777216

#define MARGIN  0.5f
#define FLAGCAP 65536

// ---- device scratch ----
__device__ __align__(128) __nv_bfloat16 g_A0[(size_t)NPIX * EDIM];  // [pix][k]
__device__ __align__(128) __nv_bfloat16 g_B0[NEMB * EDIM];          // [code][k]
__device__ __align__(16) float  g_e2[NEMB];
__device__ int    g_idx[NPIX];
__device__ double g_part[2048];
__device__ int    g_nflag;
__device__ int    g_flag[FLAGCAP];

// ---- helpers ----
static __device__ __forceinline__ uint32_t s2u(const void* p) {
    uint32_t a;
    asm("{ .reg .u64 t; cvta.to.shared.u64 t, %1; cvt.u32.u64 %0, t; }" : "=r"(a) : "l"(p));
    return a;
}
static __device__ __forceinline__ void cpa16(uint32_t dst, const void* src) {
    asm volatile("cp.async.cg.shared.global [%0], [%1], 16;" :: "r"(dst), "l"(src));
}

#define LDSM_X4(r0, r1, r2, r3, a) \
    asm volatile("ldmatrix.sync.aligned.m8n8.x4.shared.b16 {%0,%1,%2,%3}, [%4];" \
                 : "=r"(r0), "=r"(r1), "=r"(r2), "=r"(r3) : "r"(a))
#define MMA16816(d, a, b0, b1) \
    asm volatile("mma.sync.aligned.m16n8k16.row.col.f32.bf16.bf16.f32 " \
                 "{%0,%1,%2,%3}, {%4,%5,%6,%7}, {%8,%9}, {%0,%1,%2,%3};" \
                 : "+f"((d)[0]), "+f"((d)[1]), "+f"((d)[2]), "+f"((d)[3]) \
                 : "r"((a)[0]), "r"((a)[1]), "r"((a)[2]), "r"((a)[3]), "r"(b0), "r"(b1))

// ============================================================
// K1: z_e -> bf16 plane, transposed to [pix][k].
// ============================================================
__global__ __launch_bounds__(256) void k_split(const float* __restrict__ z) {
    __shared__ float sz[32][257];
    const int t = threadIdx.x;
    const int pix0 = blockIdx.x << 5;
    const float* zb = z + (((size_t)(pix0 >> 12)) << 20) + (pix0 & 4095);

    if (blockIdx.x == 0 && t == 0) g_nflag = 0;

    #pragma unroll 8
    for (int it = 0; it < 32; ++it) {
        int slot = t + (it << 8);
        int k = slot >> 5, p = slot & 31;
        sz[p][k] = zb[(size_t)k * HW + p];
    }
    __syncthreads();

    #pragma unroll
    for (int it = 0; it < 4; ++it) {
        int g = t + (it << 8);
        int p = g >> 5, k0 = (g & 31) << 3;
        union { __nv_bfloat16 h[8]; uint4 v; } u0;
        #pragma unroll
        for (int j = 0; j < 8; ++j) u0.h[j] = __float2bfloat16(sz[p][k0 + j]);
        *reinterpret_cast<uint4*>(&g_A0[((size_t)(pix0 + p) << 8) + k0]) = u0.v;
    }
}

// ============================================================
// K2: embedding -> bf16 + exact fp32 norms.
// ============================================================
__global__ __launch_bounds__(256) void k_prep_e(const float* __restrict__ emb) {
    int warp = (blockIdx.x * blockDim.x + threadIdx.x) >> 5;
    int lane = threadIdx.x & 31;
    if (warp >= NEMB) return;
    const float* row = emb + (size_t)warp * EDIM;
    int k0 = lane << 3;
    float4 v0 = *reinterpret_cast<const float4*>(row + k0);
    float4 v1 = *reinterpret_cast<const float4*>(row + k0 + 4);
    float xs[8] = {v0.x, v0.y, v0.z, v0.w, v1.x, v1.y, v1.z, v1.w};
    union { __nv_bfloat16 h[8]; uint4 v; } u0;
    float s = 0.f;
    #pragma unroll
    for (int j = 0; j < 8; ++j) {
        s += xs[j] * xs[j];
        u0.h[j] = __float2bfloat16(xs[j]);
    }
    *reinterpret_cast<uint4*>(&g_B0[((size_t)warp << 8) + k0]) = u0.v;
    #pragma unroll
    for (int o = 16; o; o >>= 1) s += __shfl_xor_sync(0xFFFFFFFFu, s, o);
    if (lane == 0) g_e2[warp] = s;
}

// ============================================================
// K3: HMMA scoring + fused argmin (R4 loop skeleton, 1 term).
// CTA = 128 pixels; warp owns 16 rows x all 128 codes of the chunk.
// 128 g-steps = 8 code-chunks x 16 k-steps of 16, double-buffered cp.async.
// smem rows: 32B payload, 80B pitch (R4's conflict-free layout).
// ============================================================
__global__ __launch_bounds__(256, 2) void k_mma1() {
    __shared__ __align__(16) char sA[2][128 * 80];
    __shared__ __align__(16) char sB[2][128 * 80];
    __shared__ float se2[NEMB];

    const int t = threadIdx.x;
    const int wid = t >> 5;
    const int lane = t & 31;
    const int pix0 = blockIdx.x << 7;

    #pragma unroll
    for (int i = 0; i < 4; ++i) se2[t + (i << 8)] = g_e2[t + (i << 8)];

    const uint32_t sAu = s2u(sA);
    const uint32_t sBu = s2u(sB);

    // cp.async roles: threads 0-127 -> A rows, 128-255 -> B rows (R4 layout)
    const bool isB = t >= 128;
    const int  row = t & 127;
    const __nv_bfloat16* P0 = isB ? g_B0 : g_A0;
    const size_t rbase = isB ? ((size_t)row << 8) : ((size_t)(pix0 + row) << 8);
    const uint32_t dbase = (isB ? sBu : sAu) + row * 80;

    // ldmatrix lane addresses (R4, unchanged)
    const uint32_t aoff = (uint32_t)((wid * 16 + (lane & 15)) * 80 + ((lane >> 4) << 4));
    const int nl = (lane & 7) + ((lane >> 4) << 3);
    const int kh = (lane >> 3) & 1;
    const uint32_t boff = (uint32_t)(nl * 80 + kh * 16);

    float rbv[2] = {3.402823466e38f, 3.402823466e38f};
    float rb2[2] = {3.402823466e38f, 3.402823466e38f};
    int   rbi[2] = {0, 0};

    float acc[16][4];

    // prime the pipeline: step 0 (kc=0, cc=0) into buffer 0
    {
        cpa16(dbase + 0,  &P0[rbase + 0]);
        cpa16(dbase + 16, &P0[rbase + 8]);
        asm volatile("cp.async.commit_group;" ::: "memory");
    }

    #pragma unroll 1
    for (int g = 0; g < 128; ++g) {
        const int buf = g & 1;
        if (g < 127) {
            const int gn = g + 1;
            const int cc = gn >> 4, kc = gn & 15;
            const size_t off = rbase + (isB ? ((size_t)cc << 15) : 0) + (kc << 4);
            const uint32_t d = dbase + ((gn & 1) ? 10240u : 0u);
            cpa16(d + 0,  &P0[off]);
            cpa16(d + 16, &P0[off + 8]);
            asm volatile("cp.async.commit_group;" ::: "memory");
            asm volatile("cp.async.wait_group 1;" ::: "memory");
        } else {
            asm volatile("cp.async.wait_group 0;" ::: "memory");
        }
        __syncthreads();

        if ((g & 15) == 0) {
            #pragma unroll
            for (int n = 0; n < 16; ++n)
                #pragma unroll
                for (int j = 0; j < 4; ++j) acc[n][j] = 0.f;
        }

        // ---- compute this k-step ----
        const uint32_t ab = sAu + (buf ? 10240u : 0u) + aoff;
        uint32_t a0[4];
        LDSM_X4(a0[0], a0[1], a0[2], a0[3], ab);

        const uint32_t bb = sBu + (buf ? 10240u : 0u) + boff;
        #pragma unroll
        for (int p = 0; p < 8; ++p) {
            uint32_t b0[4];
            LDSM_X4(b0[0], b0[1], b0[2], b0[3], bb + p * (16 * 80));
            MMA16816(acc[2 * p],     a0, b0[0], b0[1]);
            MMA16816(acc[2 * p + 1], a0, b0[2], b0[3]);
        }
        __syncthreads();

        // ---- epilogue at the end of each 128-code chunk ----
        if ((g & 15) == 15) {
            const int codebase = (g >> 4) << 7;
            #pragma unroll
            for (int s = 0; s < 2; ++s) {
                float lbv = rbv[s], lb2 = rb2[s];
                int   lbi = rbi[s];
                #pragma unroll
                for (int n = 0; n < 16; ++n) {
                    int c0 = codebase + n * 8 + ((lane & 3) << 1);
                    float s0 = fmaf(-2.f, acc[n][s * 2],     se2[c0]);
                    float s1 = fmaf(-2.f, acc[n][s * 2 + 1], se2[c0 + 1]);
                    if (s0 < lbv) { lb2 = lbv; lbv = s0; lbi = c0; }
                    else if (s0 < lb2) lb2 = s0;
                    if (s1 < lbv) { lb2 = lbv; lbv = s1; lbi = c0 + 1; }
                    else if (s1 < lb2) lb2 = s1;
                }
                rbv[s] = lbv; rb2[s] = lb2; rbi[s] = lbi;
            }
        }
    }

    // ---- merge across the 4 lanes sharing each pixel row (R7-proven) ----
    #pragma unroll
    for (int o = 1; o <= 2; o <<= 1) {
        #pragma unroll
        for (int s = 0; s < 2; ++s) {
            float ov = __shfl_xor_sync(0xFFFFFFFFu, rbv[s], o);
            float o2 = __shfl_xor_sync(0xFFFFFFFFu, rb2[s], o);
            int   oi = __shfl_xor_sync(0xFFFFFFFFu, rbi[s], o);
            if (ov < rbv[s] || (ov == rbv[s] && oi < rbi[s])) {
                rb2[s] = fminf(rbv[s], o2);
                rbv[s] = ov; rbi[s] = oi;
            } else {
                rb2[s] = fminf(rb2[s], ov);
            }
        }
    }
    if ((lane & 3) == 0) {
        #pragma unroll
        for (int s = 0; s < 2; ++s) {
            int prow = pix0 + wid * 16 + (lane >> 2) + s * 8;
            g_idx[prow] = rbi[s];
            if (rb2[s] - rbv[s] < MARGIN) {
                int pos = atomicAdd(&g_nflag, 1);
                if (pos < FLAGCAP) g_flag[pos] = prow;
            }
        }
    }
}

// ============================================================
// K4: exact fp32 rescore of margin-flagged pixels (R7-proven)
// ============================================================
__global__ __launch_bounds__(256) void k_fix(const float* __restrict__ z,
                                             const float* __restrict__ emb) {
    __shared__ float sx[8][256];
    const int w = threadIdx.x >> 5, lane = threadIdx.x & 31;
    int n = g_nflag; if (n > FLAGCAP) n = FLAGCAP;
    for (int f = blockIdx.x * 8 + w; f < n; f += gridDim.x * 8) {
        int pix = g_flag[f];
        const float* zb = z + (((size_t)(pix >> 12)) << 20) + (pix & 4095);
        for (int k = lane; k < EDIM; k += 32) sx[w][k] = zb[(size_t)k * HW];
        __syncwarp();
        float bv = 3.402823466e38f; int bi = 0;
        for (int c = lane; c < NEMB; c += 32) {
            const float* e = emb + (size_t)c * EDIM;
            float a0 = 0.f, a1 = 0.f, a2 = 0.f, a3 = 0.f;
            #pragma unroll 8
            for (int k = 0; k < EDIM; k += 4) {
                a0 = fmaf(sx[w][k],     e[k],     a0);
                a1 = fmaf(sx[w][k + 1], e[k + 1], a1);
                a2 = fmaf(sx[w][k + 2], e[k + 2], a2);
                a3 = fmaf(sx[w][k + 3], e[k + 3], a3);
            }
            float sc = g_e2[c] - 2.f * ((a0 + a1) + (a2 + a3));
            if (sc < bv) { bv = sc; bi = c; }
        }
        #pragma unroll
        for (int o = 16; o; o >>= 1) {
            float ov = __shfl_xor_sync(0xFFFFFFFFu, bv, o);
            int   oi = __shfl_xor_sync(0xFFFFFFFFu, bi, o);
            if (ov < bv || (ov == bv && oi < bi)) { bv = ov; bi = oi; }
        }
        if (lane == 0) g_idx[pix] = bi;
        __syncwarp();
    }
}

// ============================================================
// K5: gather z_q, write z_q_st = z_e + (z_q - z_e), loss partials
// ============================================================
__global__ __launch_bounds__(256)
void k_gather(const float* __restrict__ z, const float* __restrict__ emb,
              float* __restrict__ out) {
    __shared__ float sE[32 * 260];
    __shared__ float swarp[8];
    const int t = threadIdx.x;
    const int pix0 = blockIdx.x << 5;

    #pragma unroll
    for (int it = 0; it < 8; ++it) {
        int slot = t + (it << 8);
        int p = slot >> 6, c4 = slot & 63;
        int idx = g_idx[pix0 + p];
        float4 v = *reinterpret_cast<const float4*>(emb + (size_t)idx * EDIM + (c4 << 2));
        *reinterpret_cast<float4*>(&sE[p * 260 + (c4 << 2)]) = v;
    }
    __syncthreads();

    const float* zb = z   + (((size_t)(pix0 >> 12)) << 20) + (pix0 & 4095);
    float*       ob = out + (((size_t)(pix0 >> 12)) << 20) + (pix0 & 4095);

    float lsum = 0.f;
    #pragma unroll
    for (int it = 0; it < 8; ++it) {
        int slot = t + (it << 8);
        int hw = slot & 31, c4 = slot >> 5;
        float4 e = *reinterpret_cast<const float4*>(&sE[hw * 260 + (c4 << 2)]);
        float ev[4] = {e.x, e.y, e.z, e.w};
        #pragma unroll
        for (int j = 0; j < 4; ++j) {
            size_t gg = (size_t)((c4 << 2) + j) * HW + hw;
            float ze = zb[gg];
            float d = ev[j] - ze;
            ob[gg] = ze + d;
            lsum += d * d;
        }
    }
    #pragma unroll
    for (int o = 16; o; o >>= 1) lsum += __shfl_xor_sync(0xFFFFFFFFu, lsum, o);
    if ((t & 31) == 0) swarp[t >> 5] = lsum;
    __syncthreads();
    if (t == 0) {
        double s = 0.0;
        #pragma unroll
        for (int w = 0; w < 8; ++w) s += (double)swarp[w];
        g_part[blockIdx.x] = s;
    }
}

// ============================================================
// K6: loss finalize
// ============================================================
__global__ void k_loss(float* __restrict__ out, int out_size) {
    __shared__ double sd[256];
    int t = threadIdx.x;
    double s = 0.0;
    for (int i = t; i < 2048; i += 256) s += g_part[i];
    sd[t] = s;
    __syncthreads();
    for (int o = 128; o; o >>= 1) {
        if (t < o) sd[t] += sd[t + o];
        __syncthreads();
    }
    if (t == 0 && out_size > NC)
        out[NC] = (float)(0.25 * sd[0] / (double)NC);
}

// ============================================================
extern "C" void kernel_launch(void* const* d_in, const int* in_sizes, int n_in,
                              void* d_out, int out_size) {
    const float* z   = (const float*)d_in[0];
    const float* emb = (const float*)d_in[1];
    float* out = (float*)d_out;

    k_split <<<2048, 256>>>(z);
    k_prep_e<<<128,  256>>>(emb);
    k_mma1  <<<512,  256>>>();
    k_fix   <<<64,   256>>>(z, emb);
    k_gather<<<2048, 256>>>(z, emb, out);
    k_loss  <<<1,    256>>>(out, out_size);
}

// round 13
// speedup vs baseline: 7.2040x; 1.2476x over previous
#include <cuda_runtime.h>
#include <cuda_bf16.h>
#include <cstdint>
#include <cstddef>

// VectorQuantizer on GB300 (sm_103a)
// HFMA2 coarse scoring with per-step fp32 promotion + margin flag +
// exact fp32 rescore. z_e: (16,256,64,64) fp32 ; embedding: (1024,256) fp32

#define NEMB 1024
#define EDIM 256
#define HW   4096
#define NPIX 65536
#define NC   16777216

#define MARGIN  3.0f
#define FLAGCAP 65536

// smem: 3 stages x (A 4KB + B 8KB) + e2 4KB = 40KB (fits default limit)
#define STGSZ  12288
#define SM_E2  (3 * STGSZ)
#define SM_TOT (3 * STGSZ + 4096)

// ---- device scratch ----
__device__ __align__(128) __nv_bfloat16 g_AT[(size_t)EDIM * NPIX];  // [k][pix]
__device__ __align__(128) __nv_bfloat16 g_BT[EDIM * NEMB];          // [k][code]
__device__ __align__(16) float  g_e2[NEMB];
__device__ int    g_idx[NPIX];
__device__ double g_part[2048];
__device__ int    g_nflag;
__device__ int    g_flag[FLAGCAP];

static __device__ __forceinline__ uint32_t s2u(const void* p) {
    uint32_t a;
    asm("{ .reg .u64 t; cvta.to.shared.u64 t, %1; cvt.u32.u64 %0, t; }" : "=r"(a) : "l"(p));
    return a;
}
static __device__ __forceinline__ void cpa16(uint32_t dst, const void* src) {
    asm volatile("cp.async.cg.shared.global [%0], [%1], 16;" :: "r"(dst), "l"(src));
}
static __device__ __forceinline__ uint32_t bffma2(uint32_t a, uint32_t b, uint32_t c) {
    __nv_bfloat162 r = __hfma2(*reinterpret_cast<__nv_bfloat162*>(&a),
                               *reinterpret_cast<__nv_bfloat162*>(&b),
                               *reinterpret_cast<__nv_bfloat162*>(&c));
    return *reinterpret_cast<uint32_t*>(&r);
}

// ============================================================
// K1: per-code squared norms (exact fp32). One warp per code.
// ============================================================
__global__ void k_e2(const float* __restrict__ emb) {
    int warp = (blockIdx.x * blockDim.x + threadIdx.x) >> 5;
    int lane = threadIdx.x & 31;
    if (warp >= NEMB) return;
    const float4* row = reinterpret_cast<const float4*>(emb + (size_t)warp * EDIM);
    float s = 0.f;
    #pragma unroll
    for (int i = lane; i < EDIM / 4; i += 32) {
        float4 v = row[i];
        s += v.x * v.x + v.y * v.y + v.z * v.z + v.w * v.w;
    }
    #pragma unroll
    for (int o = 16; o; o >>= 1) s += __shfl_xor_sync(0xFFFFFFFFu, s, o);
    if (lane == 0) g_e2[warp] = s;
}

// ============================================================
// K2: transpose embedding -> g_BT[k][code] bf16
// ============================================================
__global__ __launch_bounds__(256) void k_bt(const float* __restrict__ emb) {
    __shared__ float tile[32][33];
    const int tx = threadIdx.x & 31;
    const int ty = threadIdx.x >> 5;          // 0..7
    const int c0 = blockIdx.x << 5;           // code tile
    const int k0 = blockIdx.y << 5;           // k tile
    #pragma unroll
    for (int i = 0; i < 4; ++i)
        tile[ty + i * 8][tx] = emb[(size_t)(c0 + ty + i * 8) * EDIM + k0 + tx];
    __syncthreads();
    #pragma unroll
    for (int i = 0; i < 4; ++i)
        g_BT[(size_t)(k0 + ty + i * 8) * NEMB + c0 + tx] =
            __float2bfloat16(tile[tx][ty + i * 8]);
}

// ============================================================
// K3: z_e -> g_AT[k][pix] bf16 (layout-preserving; R11-proven)
// ============================================================
__global__ __launch_bounds__(256) void k_prep_x(const float* __restrict__ z) {
    if (blockIdx.x == 0 && threadIdx.x == 0) g_nflag = 0;
    const float4* z4 = reinterpret_cast<const float4*>(z);
    int tid = blockIdx.x * blockDim.x + threadIdx.x;
    #pragma unroll
    for (int it = 0; it < 8; ++it) {
        int i = tid + it * 524288;
        float4 v = z4[i];
        int lin = i << 2;
        int hw = lin & 4095;
        int c  = (lin >> 12) & 255;
        int b  = lin >> 20;
        __nv_bfloat162 lo = __float22bfloat162_rn(make_float2(v.x, v.y));
        __nv_bfloat162 hi = __float22bfloat162_rn(make_float2(v.z, v.w));
        uint2 w;
        w.x = *reinterpret_cast<uint32_t*>(&lo);
        w.y = *reinterpret_cast<uint32_t*>(&hi);
        *reinterpret_cast<uint2*>(&g_AT[(size_t)c * NPIX + b * HW + hw]) = w;
    }
}

// ============================================================
// K4: HFMA2 coarse + per-step fp32 promotion + fused argmin.
// CTA = 64 pixels x 1024 codes; thread tile 4 pix x 8 codes.
// 64 steps = 8 cc x 8 kc of 32 k; 3-stage cp.async (R9-proven order).
// ============================================================
__global__ __launch_bounds__(256, 2) void k_argmin_hf() {
    extern __shared__ char smem[];
    const uint32_t sbase = s2u(smem);
    float* se2 = reinterpret_cast<float*>(smem + SM_E2);

    const int t  = threadIdx.x;
    const int tx = t & 15;             // 8 codes  (tx*8..+7)
    const int ty = t >> 4;             // 4 pixels (ty*4..+3)
    const int pix0 = blockIdx.x << 6;

    #pragma unroll
    for (int i = 0; i < 4; ++i) se2[t + (i << 8)] = g_e2[t + (i << 8)];

    // loader coords: A 256 granules (row=t>>3, col=t&7), B 512 (2 per thread)
    const int ar = t >> 3, ac = t & 7;

    // ---- prologue: issue steps 0 and 1 (cc=0, kc=p) ----
    #pragma unroll
    for (int p = 0; p < 2; ++p) {
        const uint32_t ba = sbase + p * STGSZ;
        cpa16(ba + ar * 128 + (ac << 4),
              &g_AT[(size_t)(p * 32 + ar) * NPIX + pix0 + (ac << 3)]);
        #pragma unroll
        for (int i = 0; i < 2; ++i) {
            int idx = t + (i << 8);
            int br = idx >> 4, bc = idx & 15;
            cpa16(ba + 4096 + br * 256 + (bc << 4),
                  &g_BT[(size_t)(p * 32 + br) * NEMB + (bc << 3)]);
        }
        asm volatile("cp.async.commit_group;" ::: "memory");
    }

    float bv[4], b2[4];
    int   bi[4];
    #pragma unroll
    for (int i = 0; i < 4; ++i) { bv[i] = 3.402823466e38f; b2[i] = 3.402823466e38f; bi[i] = 0; }

    uint32_t acc[4][4];
    float facc[4][8];
    #pragma unroll
    for (int i = 0; i < 4; ++i) {
        #pragma unroll
        for (int j = 0; j < 4; ++j) acc[i][j] = 0u;
        #pragma unroll
        for (int j = 0; j < 8; ++j) facc[i][j] = 0.f;
    }

    #pragma unroll 1
    for (int g = 0; g < 64; ++g) {
        // 1. own group g complete
        if (g < 63) {
            asm volatile("cp.async.wait_group 1;" ::: "memory");
        } else {
            asm volatile("cp.async.wait_group 0;" ::: "memory");
        }
        // 2. CTA-wide visibility + recycled-buffer reads done
        __syncthreads();

        // 3. issue group g+2
        if (g + 2 < 64) {
            const int g2 = g + 2;
            const int cc2 = g2 >> 3, kc2 = g2 & 7;
            const uint32_t ba = sbase + (g2 % 3) * STGSZ;
            cpa16(ba + ar * 128 + (ac << 4),
                  &g_AT[(size_t)(kc2 * 32 + ar) * NPIX + pix0 + (ac << 3)]);
            #pragma unroll
            for (int i = 0; i < 2; ++i) {
                int idx = t + (i << 8);
                int br = idx >> 4, bc = idx & 15;
                cpa16(ba + 4096 + br * 256 + (bc << 4),
                      &g_BT[(size_t)(kc2 * 32 + br) * NEMB + cc2 * 128 + (bc << 3)]);
            }
            asm volatile("cp.async.commit_group;" ::: "memory");
        }

        // 4. compute on buffer g%3
        const char* pA = smem + (g % 3) * STGSZ;
        const char* pB = pA + 4096;

        #pragma unroll 8
        for (int kk = 0; kk < 32; ++kk) {
            uint2 av = *reinterpret_cast<const uint2*>(pA + kk * 128 + (ty << 3));
            uint4 bw = *reinterpret_cast<const uint4*>(pB + kk * 256 + (tx << 4));
            uint32_t bb[4] = {bw.x, bw.y, bw.z, bw.w};
            uint32_t ad[4];
            ad[0] = __byte_perm(av.x, av.x, 0x1010);
            ad[1] = __byte_perm(av.x, av.x, 0x3232);
            ad[2] = __byte_perm(av.y, av.y, 0x1010);
            ad[3] = __byte_perm(av.y, av.y, 0x3232);
            #pragma unroll
            for (int i = 0; i < 4; ++i)
                #pragma unroll
                for (int j = 0; j < 4; ++j)
                    acc[i][j] = bffma2(ad[i], bb[j], acc[i][j]);
        }

        // ---- promote this step's bf16 partials to fp32 (exact) ----
        #pragma unroll
        for (int i = 0; i < 4; ++i)
            #pragma unroll
            for (int j = 0; j < 4; ++j) {
                uint32_t a = acc[i][j];
                acc[i][j] = 0u;
                facc[i][2 * j]     += __uint_as_float(a << 16);
                facc[i][2 * j + 1] += __uint_as_float(a & 0xFFFF0000u);
            }

        // ---- epilogue at end of each 128-code chunk ----
        if ((g & 7) == 7) {
            const int cbase = ((g >> 3) << 7) + (tx << 3);
            #pragma unroll
            for (int i = 0; i < 4; ++i) {
                #pragma unroll
                for (int j = 0; j < 8; ++j) {
                    float sc = fmaf(-2.f, facc[i][j], se2[cbase + j]);
                    facc[i][j] = 0.f;
                    int c = cbase + j;
                    if (sc < bv[i]) { b2[i] = bv[i]; bv[i] = sc; bi[i] = c; }
                    else if (sc < b2[i]) b2[i] = sc;
                }
            }
        }
    }

    // ---- merge over the 16 tx lanes sharing each pixel group ----
    #pragma unroll
    for (int o = 1; o <= 8; o <<= 1) {
        #pragma unroll
        for (int i = 0; i < 4; ++i) {
            float ov = __shfl_xor_sync(0xFFFFFFFFu, bv[i], o);
            float o2 = __shfl_xor_sync(0xFFFFFFFFu, b2[i], o);
            int   oi = __shfl_xor_sync(0xFFFFFFFFu, bi[i], o);
            if (ov < bv[i] || (ov == bv[i] && oi < bi[i])) {
                b2[i] = fminf(bv[i], o2);
                bv[i] = ov; bi[i] = oi;
            } else {
                b2[i] = fminf(b2[i], ov);
            }
        }
    }
    if (tx == 0) {
        #pragma unroll
        for (int i = 0; i < 4; ++i) {
            int prow = pix0 + (ty << 2) + i;
            g_idx[prow] = bi[i];
            if (b2[i] - bv[i] < MARGIN) {
                int pos = atomicAdd(&g_nflag, 1);
                if (pos < FLAGCAP) g_flag[pos] = prow;
            }
        }
    }
}

// ============================================================
// K5: exact fp32 rescore of margin-flagged pixels (float4 inner loop)
// ============================================================
__global__ __launch_bounds__(256) void k_fix(const float* __restrict__ z,
                                             const float* __restrict__ emb) {
    __shared__ float4 sx4[8][64];
    const int w = threadIdx.x >> 5, lane = threadIdx.x & 31;
    int n = g_nflag; if (n > FLAGCAP) n = FLAGCAP;
    for (int f = blockIdx.x * 8 + w; f < n; f += gridDim.x * 8) {
        int pix = g_flag[f];
        const float* zb = z + (((size_t)(pix >> 12)) << 20) + (pix & 4095);
        float* sxw = reinterpret_cast<float*>(sx4[w]);
        for (int k = lane; k < EDIM; k += 32) sxw[k] = zb[(size_t)k * HW];
        __syncwarp();
        float bv = 3.402823466e38f; int bi = 0;
        for (int c = lane; c < NEMB; c += 32) {
            const float4* e4 = reinterpret_cast<const float4*>(emb + (size_t)c * EDIM);
            float a0 = 0.f, a1 = 0.f, a2 = 0.f, a3 = 0.f;
            #pragma unroll 16
            for (int q = 0; q < 64; ++q) {
                float4 ev = e4[q];
                float4 xv = sx4[w][q];
                a0 = fmaf(xv.x, ev.x, a0);
                a1 = fmaf(xv.y, ev.y, a1);
                a2 = fmaf(xv.z, ev.z, a2);
                a3 = fmaf(xv.w, ev.w, a3);
            }
            float sc = g_e2[c] - 2.f * ((a0 + a1) + (a2 + a3));
            if (sc < bv) { bv = sc; bi = c; }
        }
        #pragma unroll
        for (int o = 16; o; o >>= 1) {
            float ov = __shfl_xor_sync(0xFFFFFFFFu, bv, o);
            int   oi = __shfl_xor_sync(0xFFFFFFFFu, bi, o);
            if (ov < bv || (ov == bv && oi < bi)) { bv = ov; bi = oi; }
        }
        if (lane == 0) g_idx[pix] = bi;
        __syncwarp();
    }
}

// ============================================================
// K6: gather z_q, write z_q_st = z_e + (z_q - z_e), loss partials
// ============================================================
__global__ __launch_bounds__(256)
void k_gather(const float* __restrict__ z, const float* __restrict__ emb,
              float* __restrict__ out) {
    __shared__ float sE[32 * 260];
    __shared__ float swarp[8];
    const int t = threadIdx.x;
    const int pix0 = blockIdx.x << 5;

    #pragma unroll
    for (int it = 0; it < 8; ++it) {
        int slot = t + (it << 8);
        int p = slot >> 6, c4 = slot & 63;
        int idx = g_idx[pix0 + p];
        float4 v = *reinterpret_cast<const float4*>(emb + (size_t)idx * EDIM + (c4 << 2));
        *reinterpret_cast<float4*>(&sE[p * 260 + (c4 << 2)]) = v;
    }
    __syncthreads();

    const float* zb = z   + (((size_t)(pix0 >> 12)) << 20) + (pix0 & 4095);
    float*       ob = out + (((size_t)(pix0 >> 12)) << 20) + (pix0 & 4095);

    float lsum = 0.f;
    #pragma unroll
    for (int it = 0; it < 8; ++it) {
        int slot = t + (it << 8);
        int hw = slot & 31, c4 = slot >> 5;
        float4 e = *reinterpret_cast<const float4*>(&sE[hw * 260 + (c4 << 2)]);
        float ev[4] = {e.x, e.y, e.z, e.w};
        #pragma unroll
        for (int j = 0; j < 4; ++j) {
            size_t gg = (size_t)((c4 << 2) + j) * HW + hw;
            float ze = zb[gg];
            float d = ev[j] - ze;
            ob[gg] = ze + d;
            lsum += d * d;
        }
    }
    #pragma unroll
    for (int o = 16; o; o >>= 1) lsum += __shfl_xor_sync(0xFFFFFFFFu, lsum, o);
    if ((t & 31) == 0) swarp[t >> 5] = lsum;
    __syncthreads();
    if (t == 0) {
        double s = 0.0;
        #pragma unroll
        for (int w = 0; w < 8; ++w) s += (double)swarp[w];
        g_part[blockIdx.x] = s;
    }
}

// ============================================================
// K7: loss finalize
// ============================================================
__global__ void k_loss(float* __restrict__ out, int out_size) {
    __shared__ double sd[256];
    int t = threadIdx.x;
    double s = 0.0;
    for (int i = t; i < 2048; i += 256) s += g_part[i];
    sd[t] = s;
    __syncthreads();
    for (int o = 128; o; o >>= 1) {
        if (t < o) sd[t] += sd[t + o];
        __syncthreads();
    }
    if (t == 0 && out_size > NC)
        out[NC] = (float)(0.25 * sd[0] / (double)NC);
}

// ============================================================
extern "C" void kernel_launch(void* const* d_in, const int* in_sizes, int n_in,
                              void* d_out, int out_size) {
    const float* z   = (const float*)d_in[0];
    const float* emb = (const float*)d_in[1];
    float* out = (float*)d_out;

    k_e2     <<<128, 256>>>(emb);
    {
        dim3 grid(32, 8);
        k_bt<<<grid, 256>>>(emb);
    }
    k_prep_x   <<<2048, 256>>>(z);
    k_argmin_hf<<<1024, 256, SM_TOT>>>();
    k_fix      <<<512,  256>>>(z, emb);
    k_gather   <<<2048, 256>>>(z, emb, out);
    k_loss     <<<1,    256>>>(out, out_size);
}

// round 14
// speedup vs baseline: 24.6926x; 3.4276x over previous
#include <cuda_runtime.h>
#include <cuda_fp16.h>
#include <cstdint>
#include <cstddef>

// VectorQuantizer on GB300 (sm_103a)
// fp16 HFMA2 coarse scoring (per-step fp32 promotion, sigma~0.03) +
// MARGIN 0.5 flag + exact fp32 rescore.
// z_e: (16,256,64,64) fp32 ; embedding: (1024,256) fp32

#define NEMB 1024
#define EDIM 256
#define HW   4096
#define NPIX 65536
#define NC   16777216

#define MARGIN  0.5f
#define FLAGCAP 65536

// smem: 3 stages x (A 8KB + B 8KB) + e2 4KB = 52KB
#define STGSZ  16384
#define SM_E2  (3 * STGSZ)
#define SM_TOT (3 * STGSZ + 4096)

// ---- device scratch ----
__device__ __align__(128) uint32_t g_AT2[(size_t)EDIM * NPIX];  // [k][pix] dup'd half2
__device__ __align__(128) uint32_t g_BT2[EDIM * (NEMB / 2)];    // [k][codepair] half2
__device__ __align__(16) float  g_e2[NEMB];
__device__ int    g_idx[NPIX];
__device__ double g_part[2048];
__device__ int    g_nflag;
__device__ int    g_flag[FLAGCAP];

static __device__ __forceinline__ uint32_t s2u(const void* p) {
    uint32_t a;
    asm("{ .reg .u64 t; cvta.to.shared.u64 t, %1; cvt.u32.u64 %0, t; }" : "=r"(a) : "l"(p));
    return a;
}
static __device__ __forceinline__ void cpa16(uint32_t dst, const void* src) {
    asm volatile("cp.async.cg.shared.global [%0], [%1], 16;" :: "r"(dst), "l"(src));
}
static __device__ __forceinline__ uint32_t hfma2u(uint32_t a, uint32_t b, uint32_t c) {
    __half2 r = __hfma2(*reinterpret_cast<__half2*>(&a),
                        *reinterpret_cast<__half2*>(&b),
                        *reinterpret_cast<__half2*>(&c));
    return *reinterpret_cast<uint32_t*>(&r);
}
static __device__ __forceinline__ uint32_t dup_h(float x) {
    __half h = __float2half_rn(x);
    uint16_t u = *reinterpret_cast<uint16_t*>(&h);
    return (uint32_t)u | ((uint32_t)u << 16);
}
static __device__ __forceinline__ uint32_t pair_h(float lo, float hi) {
    __half2 h = __floats2half2_rn(lo, hi);
    return *reinterpret_cast<uint32_t*>(&h);
}

// ============================================================
// K1: per-code squared norms (exact fp32). One warp per code.
// ============================================================
__global__ void k_e2(const float* __restrict__ emb) {
    int warp = (blockIdx.x * blockDim.x + threadIdx.x) >> 5;
    int lane = threadIdx.x & 31;
    if (warp >= NEMB) return;
    const float4* row = reinterpret_cast<const float4*>(emb + (size_t)warp * EDIM);
    float s = 0.f;
    #pragma unroll
    for (int i = lane; i < EDIM / 4; i += 32) {
        float4 v = row[i];
        s += v.x * v.x + v.y * v.y + v.z * v.z + v.w * v.w;
    }
    #pragma unroll
    for (int o = 16; o; o >>= 1) s += __shfl_xor_sync(0xFFFFFFFFu, s, o);
    if (lane == 0) g_e2[warp] = s;
}

// ============================================================
// K2: transpose embedding -> g_BT2[k][codepair] half2
// ============================================================
__global__ __launch_bounds__(256) void k_bt2(const float* __restrict__ emb) {
    __shared__ float tile[32][33];
    const int t  = threadIdx.x;
    const int tx = t & 31;
    const int ty = t >> 5;                    // 0..7
    const int c0 = blockIdx.x << 5;           // code tile
    const int k0 = blockIdx.y << 5;           // k tile
    #pragma unroll
    for (int i = 0; i < 4; ++i)
        tile[ty + i * 8][tx] = emb[(size_t)(c0 + ty + i * 8) * EDIM + k0 + tx];
    __syncthreads();
    #pragma unroll
    for (int it = 0; it < 2; ++it) {
        int idx = t + (it << 8);              // 0..511
        int k = idx >> 4, pr = idx & 15;
        g_BT2[(size_t)(k0 + k) * (NEMB / 2) + (c0 >> 1) + pr] =
            pair_h(tile[2 * pr][k], tile[2 * pr + 1][k]);
    }
}

// ============================================================
// K3: z_e -> g_AT2[k][pix] duplicated half2 (layout-preserving)
// ============================================================
__global__ __launch_bounds__(256) void k_prep_x(const float* __restrict__ z) {
    if (blockIdx.x == 0 && threadIdx.x == 0) g_nflag = 0;
    const float4* z4 = reinterpret_cast<const float4*>(z);
    int tid = blockIdx.x * blockDim.x + threadIdx.x;
    #pragma unroll
    for (int it = 0; it < 8; ++it) {
        int i = tid + it * 524288;
        float4 v = z4[i];
        int lin = i << 2;
        int hw = lin & 4095;
        int c  = (lin >> 12) & 255;
        int b  = lin >> 20;
        uint4 w;
        w.x = dup_h(v.x); w.y = dup_h(v.y); w.z = dup_h(v.z); w.w = dup_h(v.w);
        *reinterpret_cast<uint4*>(&g_AT2[(size_t)c * NPIX + b * HW + hw]) = w;
    }
}

// ============================================================
// K4: fp16 HFMA2 coarse + per-step fp32 promotion + fused argmin.
// CTA = 64 pixels x 1024 codes; thread tile 4 pix x 8 codes.
// 64 steps = 8 cc x 8 kc of 32 k; 3-stage cp.async (proven order).
// ============================================================
__global__ __launch_bounds__(256, 2) void k_argmin_hf() {
    extern __shared__ char smem[];
    const uint32_t sbase = s2u(smem);
    float* se2 = reinterpret_cast<float*>(smem + SM_E2);

    const int t  = threadIdx.x;
    const int tx = t & 15;             // 8 codes  (tx*8..+7)
    const int ty = t >> 4;             // 4 pixels (ty*4..+3)
    const int pix0 = blockIdx.x << 6;

    #pragma unroll
    for (int i = 0; i < 4; ++i) se2[t + (i << 8)] = g_e2[t + (i << 8)];

    // ---- prologue: issue steps 0 and 1 (cc=0, kc=p) ----
    #pragma unroll
    for (int p = 0; p < 2; ++p) {
        const uint32_t ba = sbase + p * STGSZ;
        #pragma unroll
        for (int i = 0; i < 4; ++i) {
            int idx = t + (i << 8);               // 0..1023
            if (idx < 512) {
                int kk = idx >> 4, seg = idx & 15;
                cpa16(ba + kk * 256 + (seg << 4),
                      &g_AT2[(size_t)(p * 32 + kk) * NPIX + pix0 + (seg << 2)]);
            } else {
                int gb = idx - 512, kk = gb >> 4, seg = gb & 15;
                cpa16(ba + 8192 + kk * 256 + (seg << 4),
                      &g_BT2[(size_t)(p * 32 + kk) * (NEMB / 2) + (seg << 2)]);
            }
        }
        asm volatile("cp.async.commit_group;" ::: "memory");
    }

    float bv[4], b2[4];
    int   bi[4];
    #pragma unroll
    for (int i = 0; i < 4; ++i) { bv[i] = 3.402823466e38f; b2[i] = 3.402823466e38f; bi[i] = 0; }

    uint32_t acc[4][4];
    float facc[4][8];
    #pragma unroll
    for (int i = 0; i < 4; ++i) {
        #pragma unroll
        for (int j = 0; j < 4; ++j) acc[i][j] = 0u;
        #pragma unroll
        for (int j = 0; j < 8; ++j) facc[i][j] = 0.f;
    }

    #pragma unroll 1
    for (int g = 0; g < 64; ++g) {
        // 1. own group g complete
        if (g < 63) {
            asm volatile("cp.async.wait_group 1;" ::: "memory");
        } else {
            asm volatile("cp.async.wait_group 0;" ::: "memory");
        }
        // 2. CTA-wide visibility + recycled-buffer reads done
        __syncthreads();

        // 3. issue group g+2
        if (g + 2 < 64) {
            const int g2 = g + 2;
            const int cc2 = g2 >> 3, kc2 = g2 & 7;
            const uint32_t ba = sbase + (g2 % 3) * STGSZ;
            #pragma unroll
            for (int i = 0; i < 4; ++i) {
                int idx = t + (i << 8);
                if (idx < 512) {
                    int kk = idx >> 4, seg = idx & 15;
                    cpa16(ba + kk * 256 + (seg << 4),
                          &g_AT2[(size_t)(kc2 * 32 + kk) * NPIX + pix0 + (seg << 2)]);
                } else {
                    int gb = idx - 512, kk = gb >> 4, seg = gb & 15;
                    cpa16(ba + 8192 + kk * 256 + (seg << 4),
                          &g_BT2[(size_t)(kc2 * 32 + kk) * (NEMB / 2) + cc2 * 64 + (seg << 2)]);
                }
            }
            asm volatile("cp.async.commit_group;" ::: "memory");
        }

        // 4. compute on buffer g%3
        const char* pA = smem + (g % 3) * STGSZ;
        const char* pB = pA + 8192;

        #pragma unroll 8
        for (int kk = 0; kk < 32; ++kk) {
            uint4 av = *reinterpret_cast<const uint4*>(pA + kk * 256 + (ty << 4));
            uint4 bw = *reinterpret_cast<const uint4*>(pB + kk * 256 + (tx << 4));
            uint32_t ad[4] = {av.x, av.y, av.z, av.w};
            uint32_t bb[4] = {bw.x, bw.y, bw.z, bw.w};
            #pragma unroll
            for (int i = 0; i < 4; ++i)
                #pragma unroll
                for (int j = 0; j < 4; ++j)
                    acc[i][j] = hfma2u(ad[i], bb[j], acc[i][j]);
        }

        // ---- promote this step's fp16 partials to fp32 (exact) ----
        #pragma unroll
        for (int i = 0; i < 4; ++i)
            #pragma unroll
            for (int j = 0; j < 4; ++j) {
                uint32_t a = acc[i][j];
                acc[i][j] = 0u;
                float2 f = __half22float2(*reinterpret_cast<__half2*>(&a));
                facc[i][2 * j]     += f.x;
                facc[i][2 * j + 1] += f.y;
            }

        // ---- epilogue at end of each 128-code chunk ----
        if ((g & 7) == 7) {
            const int cbase = ((g >> 3) << 7) + (tx << 3);
            #pragma unroll
            for (int i = 0; i < 4; ++i) {
                #pragma unroll
                for (int j = 0; j < 8; ++j) {
                    float sc = fmaf(-2.f, facc[i][j], se2[cbase + j]);
                    facc[i][j] = 0.f;
                    int c = cbase + j;
                    if (sc < bv[i]) { b2[i] = bv[i]; bv[i] = sc; bi[i] = c; }
                    else if (sc < b2[i]) b2[i] = sc;
                }
            }
        }
    }

    // ---- merge over the 16 tx lanes sharing each pixel group ----
    #pragma unroll
    for (int o = 1; o <= 8; o <<= 1) {
        #pragma unroll
        for (int i = 0; i < 4; ++i) {
            float ov = __shfl_xor_sync(0xFFFFFFFFu, bv[i], o);
            float o2 = __shfl_xor_sync(0xFFFFFFFFu, b2[i], o);
            int   oi = __shfl_xor_sync(0xFFFFFFFFu, bi[i], o);
            if (ov < bv[i] || (ov == bv[i] && oi < bi[i])) {
                b2[i] = fminf(bv[i], o2);
                bv[i] = ov; bi[i] = oi;
            } else {
                b2[i] = fminf(b2[i], ov);
            }
        }
    }
    if (tx == 0) {
        #pragma unroll
        for (int i = 0; i < 4; ++i) {
            int prow = pix0 + (ty << 2) + i;
            g_idx[prow] = bi[i];
            if (b2[i] - bv[i] < MARGIN) {
                int pos = atomicAdd(&g_nflag, 1);
                if (pos < FLAGCAP) g_flag[pos] = prow;
            }
        }
    }
}

// ============================================================
// K5: exact fp32 rescore of margin-flagged pixels
// ============================================================
__global__ __launch_bounds__(256) void k_fix(const float* __restrict__ z,
                                             const float* __restrict__ emb) {
    __shared__ float4 sx4[8][64];
    const int w = threadIdx.x >> 5, lane = threadIdx.x & 31;
    int n = g_nflag; if (n > FLAGCAP) n = FLAGCAP;
    for (int f = blockIdx.x * 8 + w; f < n; f += gridDim.x * 8) {
        int pix = g_flag[f];
        const float* zb = z + (((size_t)(pix >> 12)) << 20) + (pix & 4095);
        float* sxw = reinterpret_cast<float*>(sx4[w]);
        for (int k = lane; k < EDIM; k += 32) sxw[k] = zb[(size_t)k * HW];
        __syncwarp();
        float bv = 3.402823466e38f; int bi = 0;
        for (int c = lane; c < NEMB; c += 32) {
            const float4* e4 = reinterpret_cast<const float4*>(emb + (size_t)c * EDIM);
            float a0 = 0.f, a1 = 0.f, a2 = 0.f, a3 = 0.f;
            #pragma unroll 16
            for (int q = 0; q < 64; ++q) {
                float4 ev = e4[q];
                float4 xv = sx4[w][q];
                a0 = fmaf(xv.x, ev.x, a0);
                a1 = fmaf(xv.y, ev.y, a1);
                a2 = fmaf(xv.z, ev.z, a2);
                a3 = fmaf(xv.w, ev.w, a3);
            }
            float sc = g_e2[c] - 2.f * ((a0 + a1) + (a2 + a3));
            if (sc < bv) { bv = sc; bi = c; }
        }
        #pragma unroll
        for (int o = 16; o; o >>= 1) {
            float ov = __shfl_xor_sync(0xFFFFFFFFu, bv, o);
            int   oi = __shfl_xor_sync(0xFFFFFFFFu, bi, o);
            if (ov < bv || (ov == bv && oi < bi)) { bv = ov; bi = oi; }
        }
        if (lane == 0) g_idx[pix] = bi;
        __syncwarp();
    }
}

// ============================================================
// K6: gather z_q, write z_q_st = z_e + (z_q - z_e), loss partials
// ============================================================
__global__ __launch_bounds__(256)
void k_gather(const float* __restrict__ z, const float* __restrict__ emb,
              float* __restrict__ out) {
    __shared__ float sE[32 * 260];
    __shared__ float swarp[8];
    const int t = threadIdx.x;
    const int pix0 = blockIdx.x << 5;

    #pragma unroll
    for (int it = 0; it < 8; ++it) {
        int slot = t + (it << 8);
        int p = slot >> 6, c4 = slot & 63;
        int idx = g_idx[pix0 + p];
        float4 v = *reinterpret_cast<const float4*>(emb + (size_t)idx * EDIM + (c4 << 2));
        *reinterpret_cast<float4*>(&sE[p * 260 + (c4 << 2)]) = v;
    }
    __syncthreads();

    const float* zb = z   + (((size_t)(pix0 >> 12)) << 20) + (pix0 & 4095);
    float*       ob = out + (((size_t)(pix0 >> 12)) << 20) + (pix0 & 4095);

    float lsum = 0.f;
    #pragma unroll
    for (int it = 0; it < 8; ++it) {
        int slot = t + (it << 8);
        int hw = slot & 31, c4 = slot >> 5;
        float4 e = *reinterpret_cast<const float4*>(&sE[hw * 260 + (c4 << 2)]);
        float ev[4] = {e.x, e.y, e.z, e.w};
        #pragma unroll
        for (int j = 0; j < 4; ++j) {
            size_t gg = (size_t)((c4 << 2) + j) * HW + hw;
            float ze = zb[gg];
            float d = ev[j] - ze;
            ob[gg] = ze + d;
            lsum += d * d;
        }
    }
    #pragma unroll
    for (int o = 16; o; o >>= 1) lsum += __shfl_xor_sync(0xFFFFFFFFu, lsum, o);
    if ((t & 31) == 0) swarp[t >> 5] = lsum;
    __syncthreads();
    if (t == 0) {
        double s = 0.0;
        #pragma unroll
        for (int w = 0; w < 8; ++w) s += (double)swarp[w];
        g_part[blockIdx.x] = s;
    }
}

// ============================================================
// K7: loss finalize
// ============================================================
__global__ void k_loss(float* __restrict__ out, int out_size) {
    __shared__ double sd[256];
    int t = threadIdx.x;
    double s = 0.0;
    for (int i = t; i < 2048; i += 256) s += g_part[i];
    sd[t] = s;
    __syncthreads();
    for (int o = 128; o; o >>= 1) {
        if (t < o) sd[t] += sd[t + o];
        __syncthreads();
    }
    if (t == 0 && out_size > NC)
        out[NC] = (float)(0.25 * sd[0] / (double)NC);
}

// ============================================================
extern "C" void kernel_launch(void* const* d_in, const int* in_sizes, int n_in,
                              void* d_out, int out_size) {
    const float* z   = (const float*)d_in[0];
    const float* emb = (const float*)d_in[1];
    float* out = (float*)d_out;

    cudaFuncSetAttribute(k_argmin_hf, cudaFuncAttributeMaxDynamicSharedMemorySize, SM_TOT);

    k_e2     <<<128, 256>>>(emb);
    {
        dim3 grid(32, 8);
        k_bt2<<<grid, 256>>>(emb);
    }
    k_prep_x   <<<2048, 256>>>(z);
    k_argmin_hf<<<1024, 256, SM_TOT>>>();
    k_fix      <<<512,  256>>>(z, emb);
    k_gather   <<<2048, 256>>>(z, emb, out);
    k_loss     <<<1,    256>>>(out, out_size);
}

// round 15
// speedup vs baseline: 39.4455x; 1.5975x over previous
#include <cuda_runtime.h>
#include <cuda_fp16.h>
#include <cstdint>
#include <cstddef>

// VectorQuantizer on GB300 (sm_103a)
// fp16 HFMA2 coarse scoring (per-step fp32 promotion) + MARGIN 0.5 flag +
// exact fp32 rescore (coalesced k-split). z_e: (16,256,64,64) fp32 ;
// embedding: (1024,256) fp32

#define NEMB 1024
#define EDIM 256
#define HW   4096
#define NPIX 65536
#define NC   16777216

#define MARGIN  0.5f
#define FLAGCAP 65536

// smem: 3 stages x (A 8KB + B 8KB) + e2 4KB = 52KB
#define STGSZ  16384
#define SM_E2  (3 * STGSZ)
#define SM_TOT (3 * STGSZ + 4096)

// ---- device scratch ----
__device__ __align__(128) uint32_t g_AT2[(size_t)EDIM * NPIX];  // [k][pix] dup'd half2
__device__ __align__(128) uint32_t g_BT2[EDIM * (NEMB / 2)];    // [k][codepair] half2
__device__ __align__(16) float  g_e2[NEMB];
__device__ int    g_idx[NPIX];
__device__ double g_part[2048];
__device__ int    g_nflag;
__device__ int    g_flag[FLAGCAP];

static __device__ __forceinline__ uint32_t s2u(const void* p) {
    uint32_t a;
    asm("{ .reg .u64 t; cvta.to.shared.u64 t, %1; cvt.u32.u64 %0, t; }" : "=r"(a) : "l"(p));
    return a;
}
static __device__ __forceinline__ void cpa16(uint32_t dst, const void* src) {
    asm volatile("cp.async.cg.shared.global [%0], [%1], 16;" :: "r"(dst), "l"(src));
}
static __device__ __forceinline__ uint32_t hfma2u(uint32_t a, uint32_t b, uint32_t c) {
    __half2 r = __hfma2(*reinterpret_cast<__half2*>(&a),
                        *reinterpret_cast<__half2*>(&b),
                        *reinterpret_cast<__half2*>(&c));
    return *reinterpret_cast<uint32_t*>(&r);
}
static __device__ __forceinline__ uint32_t dup_h(float x) {
    __half h = __float2half_rn(x);
    uint16_t u = *reinterpret_cast<uint16_t*>(&h);
    return (uint32_t)u | ((uint32_t)u << 16);
}
static __device__ __forceinline__ uint32_t pair_h(float lo, float hi) {
    __half2 h = __floats2half2_rn(lo, hi);
    return *reinterpret_cast<uint32_t*>(&h);
}

// ============================================================
// K1: per-code squared norms (exact fp32). One warp per code.
// ============================================================
__global__ void k_e2(const float* __restrict__ emb) {
    int warp = (blockIdx.x * blockDim.x + threadIdx.x) >> 5;
    int lane = threadIdx.x & 31;
    if (warp >= NEMB) return;
    const float4* row = reinterpret_cast<const float4*>(emb + (size_t)warp * EDIM);
    float s = 0.f;
    #pragma unroll
    for (int i = lane; i < EDIM / 4; i += 32) {
        float4 v = row[i];
        s += v.x * v.x + v.y * v.y + v.z * v.z + v.w * v.w;
    }
    #pragma unroll
    for (int o = 16; o; o >>= 1) s += __shfl_xor_sync(0xFFFFFFFFu, s, o);
    if (lane == 0) g_e2[warp] = s;
}

// ============================================================
// K2: transpose embedding -> g_BT2[k][codepair] half2
// ============================================================
__global__ __launch_bounds__(256) void k_bt2(const float* __restrict__ emb) {
    __shared__ float tile[32][33];
    const int t  = threadIdx.x;
    const int tx = t & 31;
    const int ty = t >> 5;                    // 0..7
    const int c0 = blockIdx.x << 5;           // code tile
    const int k0 = blockIdx.y << 5;           // k tile
    #pragma unroll
    for (int i = 0; i < 4; ++i)
        tile[ty + i * 8][tx] = emb[(size_t)(c0 + ty + i * 8) * EDIM + k0 + tx];
    __syncthreads();
    #pragma unroll
    for (int it = 0; it < 2; ++it) {
        int idx = t + (it << 8);              // 0..511
        int k = idx >> 4, pr = idx & 15;
        g_BT2[(size_t)(k0 + k) * (NEMB / 2) + (c0 >> 1) + pr] =
            pair_h(tile[2 * pr][k], tile[2 * pr + 1][k]);
    }
}

// ============================================================
// K3: z_e -> g_AT2[k][pix] duplicated half2 (layout-preserving)
// ============================================================
__global__ __launch_bounds__(256) void k_prep_x(const float* __restrict__ z) {
    if (blockIdx.x == 0 && threadIdx.x == 0) g_nflag = 0;
    const float4* z4 = reinterpret_cast<const float4*>(z);
    int tid = blockIdx.x * blockDim.x + threadIdx.x;
    #pragma unroll
    for (int it = 0; it < 8; ++it) {
        int i = tid + it * 524288;
        float4 v = z4[i];
        int lin = i << 2;
        int hw = lin & 4095;
        int c  = (lin >> 12) & 255;
        int b  = lin >> 20;
        uint4 w;
        w.x = dup_h(v.x); w.y = dup_h(v.y); w.z = dup_h(v.z); w.w = dup_h(v.w);
        *reinterpret_cast<uint4*>(&g_AT2[(size_t)c * NPIX + b * HW + hw]) = w;
    }
}

// ============================================================
// K4: fp16 HFMA2 coarse + per-step fp32 promotion + fused argmin.
// (byte-identical to R14's 572.9us kernel)
// ============================================================
__global__ __launch_bounds__(256, 2) void k_argmin_hf() {
    extern __shared__ char smem[];
    const uint32_t sbase = s2u(smem);
    float* se2 = reinterpret_cast<float*>(smem + SM_E2);

    const int t  = threadIdx.x;
    const int tx = t & 15;             // 8 codes  (tx*8..+7)
    const int ty = t >> 4;             // 4 pixels (ty*4..+3)
    const int pix0 = blockIdx.x << 6;

    #pragma unroll
    for (int i = 0; i < 4; ++i) se2[t + (i << 8)] = g_e2[t + (i << 8)];

    #pragma unroll
    for (int p = 0; p < 2; ++p) {
        const uint32_t ba = sbase + p * STGSZ;
        #pragma unroll
        for (int i = 0; i < 4; ++i) {
            int idx = t + (i << 8);
            if (idx < 512) {
                int kk = idx >> 4, seg = idx & 15;
                cpa16(ba + kk * 256 + (seg << 4),
                      &g_AT2[(size_t)(p * 32 + kk) * NPIX + pix0 + (seg << 2)]);
            } else {
                int gb = idx - 512, kk = gb >> 4, seg = gb & 15;
                cpa16(ba + 8192 + kk * 256 + (seg << 4),
                      &g_BT2[(size_t)(p * 32 + kk) * (NEMB / 2) + (seg << 2)]);
            }
        }
        asm volatile("cp.async.commit_group;" ::: "memory");
    }

    float bv[4], b2[4];
    int   bi[4];
    #pragma unroll
    for (int i = 0; i < 4; ++i) { bv[i] = 3.402823466e38f; b2[i] = 3.402823466e38f; bi[i] = 0; }

    uint32_t acc[4][4];
    float facc[4][8];
    #pragma unroll
    for (int i = 0; i < 4; ++i) {
        #pragma unroll
        for (int j = 0; j < 4; ++j) acc[i][j] = 0u;
        #pragma unroll
        for (int j = 0; j < 8; ++j) facc[i][j] = 0.f;
    }

    #pragma unroll 1
    for (int g = 0; g < 64; ++g) {
        if (g < 63) {
            asm volatile("cp.async.wait_group 1;" ::: "memory");
        } else {
            asm volatile("cp.async.wait_group 0;" ::: "memory");
        }
        __syncthreads();

        if (g + 2 < 64) {
            const int g2 = g + 2;
            const int cc2 = g2 >> 3, kc2 = g2 & 7;
            const uint32_t ba = sbase + (g2 % 3) * STGSZ;
            #pragma unroll
            for (int i = 0; i < 4; ++i) {
                int idx = t + (i << 8);
                if (idx < 512) {
                    int kk = idx >> 4, seg = idx & 15;
                    cpa16(ba + kk * 256 + (seg << 4),
                          &g_AT2[(size_t)(kc2 * 32 + kk) * NPIX + pix0 + (seg << 2)]);
                } else {
                    int gb = idx - 512, kk = gb >> 4, seg = gb & 15;
                    cpa16(ba + 8192 + kk * 256 + (seg << 4),
                          &g_BT2[(size_t)(kc2 * 32 + kk) * (NEMB / 2) + cc2 * 64 + (seg << 2)]);
                }
            }
            asm volatile("cp.async.commit_group;" ::: "memory");
        }

        const char* pA = smem + (g % 3) * STGSZ;
        const char* pB = pA + 8192;

        #pragma unroll 8
        for (int kk = 0; kk < 32; ++kk) {
            uint4 av = *reinterpret_cast<const uint4*>(pA + kk * 256 + (ty << 4));
            uint4 bw = *reinterpret_cast<const uint4*>(pB + kk * 256 + (tx << 4));
            uint32_t ad[4] = {av.x, av.y, av.z, av.w};
            uint32_t bb[4] = {bw.x, bw.y, bw.z, bw.w};
            #pragma unroll
            for (int i = 0; i < 4; ++i)
                #pragma unroll
                for (int j = 0; j < 4; ++j)
                    acc[i][j] = hfma2u(ad[i], bb[j], acc[i][j]);
        }

        #pragma unroll
        for (int i = 0; i < 4; ++i)
            #pragma unroll
            for (int j = 0; j < 4; ++j) {
                uint32_t a = acc[i][j];
                acc[i][j] = 0u;
                float2 f = __half22float2(*reinterpret_cast<__half2*>(&a));
                facc[i][2 * j]     += f.x;
                facc[i][2 * j + 1] += f.y;
            }

        if ((g & 7) == 7) {
            const int cbase = ((g >> 3) << 7) + (tx << 3);
            #pragma unroll
            for (int i = 0; i < 4; ++i) {
                #pragma unroll
                for (int j = 0; j < 8; ++j) {
                    float sc = fmaf(-2.f, facc[i][j], se2[cbase + j]);
                    facc[i][j] = 0.f;
                    int c = cbase + j;
                    if (sc < bv[i]) { b2[i] = bv[i]; bv[i] = sc; bi[i] = c; }
                    else if (sc < b2[i]) b2[i] = sc;
                }
            }
        }
    }

    #pragma unroll
    for (int o = 1; o <= 8; o <<= 1) {
        #pragma unroll
        for (int i = 0; i < 4; ++i) {
            float ov = __shfl_xor_sync(0xFFFFFFFFu, bv[i], o);
            float o2 = __shfl_xor_sync(0xFFFFFFFFu, b2[i], o);
            int   oi = __shfl_xor_sync(0xFFFFFFFFu, bi[i], o);
            if (ov < bv[i] || (ov == bv[i] && oi < bi[i])) {
                b2[i] = fminf(bv[i], o2);
                bv[i] = ov; bi[i] = oi;
            } else {
                b2[i] = fminf(b2[i], ov);
            }
        }
    }
    if (tx == 0) {
        #pragma unroll
        for (int i = 0; i < 4; ++i) {
            int prow = pix0 + (ty << 2) + i;
            g_idx[prow] = bi[i];
            if (b2[i] - bv[i] < MARGIN) {
                int pos = atomicAdd(&g_nflag, 1);
                if (pos < FLAGCAP) g_flag[pos] = prow;
            }
        }
    }
}

// ============================================================
// K5: exact fp32 rescore — coalesced k-split version.
// Warp per flagged pixel; lane l holds x[8l..8l+7] in registers;
// each code's 256-float row read coalesced; fixed-order butterfly.
// ============================================================
__global__ __launch_bounds__(256) void k_fix(const float* __restrict__ z,
                                             const float* __restrict__ emb) {
    const int w = threadIdx.x >> 5, lane = threadIdx.x & 31;
    int n = g_nflag; if (n > FLAGCAP) n = FLAGCAP;
    for (int f = blockIdx.x * 8 + w; f < n; f += gridDim.x * 8) {
        int pix = g_flag[f];
        const float* zb = z + (((size_t)(pix >> 12)) << 20) + (pix & 4095);
        // lane-resident x slice: x[8*lane .. 8*lane+7]
        float xr[8];
        #pragma unroll
        for (int j = 0; j < 8; ++j) xr[j] = zb[(size_t)(lane * 8 + j) * HW];

        float bv = 3.402823466e38f; int bi = 0;
        #pragma unroll 1
        for (int c = 0; c < NEMB; c += 2) {
            const float4* e0 = reinterpret_cast<const float4*>(emb + (size_t)c * EDIM) + lane * 2;
            const float4* e1 = reinterpret_cast<const float4*>(emb + (size_t)(c + 1) * EDIM) + lane * 2;
            float4 a0 = e0[0], a1 = e0[1];
            float4 c0 = e1[0], c1 = e1[1];
            float s0 = xr[0] * a0.x, s1 = xr[0] * c0.x;
            s0 = fmaf(xr[1], a0.y, s0); s1 = fmaf(xr[1], c0.y, s1);
            s0 = fmaf(xr[2], a0.z, s0); s1 = fmaf(xr[2], c0.z, s1);
            s0 = fmaf(xr[3], a0.w, s0); s1 = fmaf(xr[3], c0.w, s1);
            s0 = fmaf(xr[4], a1.x, s0); s1 = fmaf(xr[4], c1.x, s1);
            s0 = fmaf(xr[5], a1.y, s0); s1 = fmaf(xr[5], c1.y, s1);
            s0 = fmaf(xr[6], a1.z, s0); s1 = fmaf(xr[6], c1.z, s1);
            s0 = fmaf(xr[7], a1.w, s0); s1 = fmaf(xr[7], c1.w, s1);
            #pragma unroll
            for (int o = 16; o; o >>= 1) {
                s0 += __shfl_xor_sync(0xFFFFFFFFu, s0, o);
                s1 += __shfl_xor_sync(0xFFFFFFFFu, s1, o);
            }
            float sc0 = g_e2[c]     - 2.f * s0;
            float sc1 = g_e2[c + 1] - 2.f * s1;
            if (sc0 < bv) { bv = sc0; bi = c; }
            if (sc1 < bv) { bv = sc1; bi = c + 1; }
        }
        if (lane == 0) g_idx[pix] = bi;
        __syncwarp();
    }
}

// ============================================================
// K6: gather z_q, write z_q_st = z_e + (z_q - z_e), loss partials
// ============================================================
__global__ __launch_bounds__(256)
void k_gather(const float* __restrict__ z, const float* __restrict__ emb,
              float* __restrict__ out) {
    __shared__ float sE[32 * 260];
    __shared__ float swarp[8];
    const int t = threadIdx.x;
    const int pix0 = blockIdx.x << 5;

    #pragma unroll
    for (int it = 0; it < 8; ++it) {
        int slot = t + (it << 8);
        int p = slot >> 6, c4 = slot & 63;
        int idx = g_idx[pix0 + p];
        float4 v = *reinterpret_cast<const float4*>(emb + (size_t)idx * EDIM + (c4 << 2));
        *reinterpret_cast<float4*>(&sE[p * 260 + (c4 << 2)]) = v;
    }
    __syncthreads();

    const float* zb = z   + (((size_t)(pix0 >> 12)) << 20) + (pix0 & 4095);
    float*       ob = out + (((size_t)(pix0 >> 12)) << 20) + (pix0 & 4095);

    float lsum = 0.f;
    #pragma unroll
    for (int it = 0; it < 8; ++it) {
        int slot = t + (it << 8);
        int hw = slot & 31, c4 = slot >> 5;
        float4 e = *reinterpret_cast<const float4*>(&sE[hw * 260 + (c4 << 2)]);
        float ev[4] = {e.x, e.y, e.z, e.w};
        #pragma unroll
        for (int j = 0; j < 4; ++j) {
            size_t gg = (size_t)((c4 << 2) + j) * HW + hw;
            float ze = zb[gg];
            float d = ev[j] - ze;
            ob[gg] = ze + d;
            lsum += d * d;
        }
    }
    #pragma unroll
    for (int o = 16; o; o >>= 1) lsum += __shfl_xor_sync(0xFFFFFFFFu, lsum, o);
    if ((t & 31) == 0) swarp[t >> 5] = lsum;
    __syncthreads();
    if (t == 0) {
        double s = 0.0;
        #pragma unroll
        for (int w = 0; w < 8; ++w) s += (double)swarp[w];
        g_part[blockIdx.x] = s;
    }
}

// ============================================================
// K7: loss finalize
// ============================================================
__global__ void k_loss(float* __restrict__ out, int out_size) {
    __shared__ double sd[256];
    int t = threadIdx.x;
    double s = 0.0;
    for (int i = t; i < 2048; i += 256) s += g_part[i];
    sd[t] = s;
    __syncthreads();
    for (int o = 128; o; o >>= 1) {
        if (t < o) sd[t] += sd[t + o];
        __syncthreads();
    }
    if (t == 0 && out_size > NC)
        out[NC] = (float)(0.25 * sd[0] / (double)NC);
}

// ============================================================
extern "C" void kernel_launch(void* const* d_in, const int* in_sizes, int n_in,
                              void* d_out, int out_size) {
    const float* z   = (const float*)d_in[0];
    const float* emb = (const float*)d_in[1];
    float* out = (float*)d_out;

    cudaFuncSetAttribute(k_argmin_hf, cudaFuncAttributeMaxDynamicSharedMemorySize, SM_TOT);

    k_e2     <<<128, 256>>>(emb);
    {
        dim3 grid(32, 8);
        k_bt2<<<grid, 256>>>(emb);
    }
    k_prep_x   <<<2048, 256>>>(z);
    k_argmin_hf<<<1024, 256, SM_TOT>>>();
    k_fix      <<<512,  256>>>(z, emb);
    k_gather   <<<2048, 256>>>(z, emb, out);
    k_loss     <<<1,    256>>>(out, out_size);
}

// round 16
// speedup vs baseline: 39.6618x; 1.0055x over previous
#include <cuda_runtime.h>
#include <cuda_fp16.h>
#include <cstdint>
#include <cstddef>

// VectorQuantizer on GB300 (sm_103a)
// fp16 HFMA2 coarse scan (top-2 idx + 3rd value) + candidate-pair exact fixup
// (A) + full exact rescan for rare 3-way ties (B).
// z_e: (16,256,64,64) fp32 ; embedding: (1024,256) fp32

#define NEMB 1024
#define EDIM 256
#define HW   4096
#define NPIX 65536
#define NC   16777216

#define MARGIN  0.5f
#define FLAGCAPA 65536
#define FLAGCAPB 16384

// smem: 3 stages x (A 8KB + B 8KB) + e2 4KB = 52KB
#define STGSZ  16384
#define SM_E2  (3 * STGSZ)
#define SM_TOT (3 * STGSZ + 4096)

// ---- device scratch ----
__device__ __align__(128) uint32_t g_AT2[(size_t)EDIM * NPIX];  // [k][pix] dup'd half2
__device__ __align__(128) uint32_t g_BT2[EDIM * (NEMB / 2)];    // [k][codepair] half2
__device__ __align__(16) float  g_e2[NEMB];
__device__ int    g_idx[NPIX];
__device__ double g_part[2048];
__device__ int    g_nA, g_nB;
__device__ int    g_flagA[FLAGCAPA];
__device__ int2   g_candA[FLAGCAPA];
__device__ int    g_flagB[FLAGCAPB];

static __device__ __forceinline__ uint32_t s2u(const void* p) {
    uint32_t a;
    asm("{ .reg .u64 t; cvta.to.shared.u64 t, %1; cvt.u32.u64 %0, t; }" : "=r"(a) : "l"(p));
    return a;
}
static __device__ __forceinline__ void cpa16(uint32_t dst, const void* src) {
    asm volatile("cp.async.cg.shared.global [%0], [%1], 16;" :: "r"(dst), "l"(src));
}
static __device__ __forceinline__ uint32_t hfma2u(uint32_t a, uint32_t b, uint32_t c) {
    __half2 r = __hfma2(*reinterpret_cast<__half2*>(&a),
                        *reinterpret_cast<__half2*>(&b),
                        *reinterpret_cast<__half2*>(&c));
    return *reinterpret_cast<uint32_t*>(&r);
}
static __device__ __forceinline__ uint32_t dup_h(float x) {
    __half h = __float2half_rn(x);
    uint16_t u = *reinterpret_cast<uint16_t*>(&h);
    return (uint32_t)u | ((uint32_t)u << 16);
}
static __device__ __forceinline__ uint32_t pair_h(float lo, float hi) {
    __half2 h = __floats2half2_rn(lo, hi);
    return *reinterpret_cast<uint32_t*>(&h);
}

// ============================================================
// K1: per-code squared norms (exact fp32). One warp per code.
// ============================================================
__global__ void k_e2(const float* __restrict__ emb) {
    int warp = (blockIdx.x * blockDim.x + threadIdx.x) >> 5;
    int lane = threadIdx.x & 31;
    if (warp >= NEMB) return;
    const float4* row = reinterpret_cast<const float4*>(emb + (size_t)warp * EDIM);
    float s = 0.f;
    #pragma unroll
    for (int i = lane; i < EDIM / 4; i += 32) {
        float4 v = row[i];
        s += v.x * v.x + v.y * v.y + v.z * v.z + v.w * v.w;
    }
    #pragma unroll
    for (int o = 16; o; o >>= 1) s += __shfl_xor_sync(0xFFFFFFFFu, s, o);
    if (lane == 0) g_e2[warp] = s;
}

// ============================================================
// K2: transpose embedding -> g_BT2[k][codepair] half2
// ============================================================
__global__ __launch_bounds__(256) void k_bt2(const float* __restrict__ emb) {
    __shared__ float tile[32][33];
    const int t  = threadIdx.x;
    const int tx = t & 31;
    const int ty = t >> 5;
    const int c0 = blockIdx.x << 5;
    const int k0 = blockIdx.y << 5;
    #pragma unroll
    for (int i = 0; i < 4; ++i)
        tile[ty + i * 8][tx] = emb[(size_t)(c0 + ty + i * 8) * EDIM + k0 + tx];
    __syncthreads();
    #pragma unroll
    for (int it = 0; it < 2; ++it) {
        int idx = t + (it << 8);
        int k = idx >> 4, pr = idx & 15;
        g_BT2[(size_t)(k0 + k) * (NEMB / 2) + (c0 >> 1) + pr] =
            pair_h(tile[2 * pr][k], tile[2 * pr + 1][k]);
    }
}

// ============================================================
// K3: z_e -> g_AT2[k][pix] duplicated half2 (layout-preserving)
// ============================================================
__global__ __launch_bounds__(256) void k_prep_x(const float* __restrict__ z) {
    if (blockIdx.x == 0 && threadIdx.x == 0) { g_nA = 0; g_nB = 0; }
    const float4* z4 = reinterpret_cast<const float4*>(z);
    int tid = blockIdx.x * blockDim.x + threadIdx.x;
    #pragma unroll
    for (int it = 0; it < 8; ++it) {
        int i = tid + it * 524288;
        float4 v = z4[i];
        int lin = i << 2;
        int hw = lin & 4095;
        int c  = (lin >> 12) & 255;
        int b  = lin >> 20;
        uint4 w;
        w.x = dup_h(v.x); w.y = dup_h(v.y); w.z = dup_h(v.z); w.w = dup_h(v.w);
        *reinterpret_cast<uint4*>(&g_AT2[(size_t)c * NPIX + b * HW + hw]) = w;
    }
}

// ============================================================
// K4: fp16 HFMA2 coarse + per-step fp32 promotion + top-2idx/3rd-val argmin.
// (loop structure identical to R14/R15's 572.9us kernel)
// ============================================================
__global__ __launch_bounds__(256, 2) void k_argmin_hf() {
    extern __shared__ char smem[];
    const uint32_t sbase = s2u(smem);
    float* se2 = reinterpret_cast<float*>(smem + SM_E2);

    const int t  = threadIdx.x;
    const int tx = t & 15;             // 8 codes  (tx*8..+7)
    const int ty = t >> 4;             // 4 pixels (ty*4..+3)
    const int pix0 = blockIdx.x << 6;

    #pragma unroll
    for (int i = 0; i < 4; ++i) se2[t + (i << 8)] = g_e2[t + (i << 8)];

    #pragma unroll
    for (int p = 0; p < 2; ++p) {
        const uint32_t ba = sbase + p * STGSZ;
        #pragma unroll
        for (int i = 0; i < 4; ++i) {
            int idx = t + (i << 8);
            if (idx < 512) {
                int kk = idx >> 4, seg = idx & 15;
                cpa16(ba + kk * 256 + (seg << 4),
                      &g_AT2[(size_t)(p * 32 + kk) * NPIX + pix0 + (seg << 2)]);
            } else {
                int gb = idx - 512, kk = gb >> 4, seg = gb & 15;
                cpa16(ba + 8192 + kk * 256 + (seg << 4),
                      &g_BT2[(size_t)(p * 32 + kk) * (NEMB / 2) + (seg << 2)]);
            }
        }
        asm volatile("cp.async.commit_group;" ::: "memory");
    }

    float bv[4], b2[4], b3[4];
    int   bi[4], b2i[4];
    #pragma unroll
    for (int i = 0; i < 4; ++i) {
        bv[i] = 3.402823466e38f; b2[i] = 3.402823466e38f; b3[i] = 3.402823466e38f;
        bi[i] = 0; b2i[i] = 0;
    }

    uint32_t acc[4][4];
    float facc[4][8];
    #pragma unroll
    for (int i = 0; i < 4; ++i) {
        #pragma unroll
        for (int j = 0; j < 4; ++j) acc[i][j] = 0u;
        #pragma unroll
        for (int j = 0; j < 8; ++j) facc[i][j] = 0.f;
    }

    #pragma unroll 1
    for (int g = 0; g < 64; ++g) {
        if (g < 63) {
            asm volatile("cp.async.wait_group 1;" ::: "memory");
        } else {
            asm volatile("cp.async.wait_group 0;" ::: "memory");
        }
        __syncthreads();

        if (g + 2 < 64) {
            const int g2 = g + 2;
            const int cc2 = g2 >> 3, kc2 = g2 & 7;
            const uint32_t ba = sbase + (g2 % 3) * STGSZ;
            #pragma unroll
            for (int i = 0; i < 4; ++i) {
                int idx = t + (i << 8);
                if (idx < 512) {
                    int kk = idx >> 4, seg = idx & 15;
                    cpa16(ba + kk * 256 + (seg << 4),
                          &g_AT2[(size_t)(kc2 * 32 + kk) * NPIX + pix0 + (seg << 2)]);
                } else {
                    int gb = idx - 512, kk = gb >> 4, seg = gb & 15;
                    cpa16(ba + 8192 + kk * 256 + (seg << 4),
                          &g_BT2[(size_t)(kc2 * 32 + kk) * (NEMB / 2) + cc2 * 64 + (seg << 2)]);
                }
            }
            asm volatile("cp.async.commit_group;" ::: "memory");
        }

        const char* pA = smem + (g % 3) * STGSZ;
        const char* pB = pA + 8192;

        #pragma unroll 8
        for (int kk = 0; kk < 32; ++kk) {
            uint4 av = *reinterpret_cast<const uint4*>(pA + kk * 256 + (ty << 4));
            uint4 bw = *reinterpret_cast<const uint4*>(pB + kk * 256 + (tx << 4));
            uint32_t ad[4] = {av.x, av.y, av.z, av.w};
            uint32_t bb[4] = {bw.x, bw.y, bw.z, bw.w};
            #pragma unroll
            for (int i = 0; i < 4; ++i)
                #pragma unroll
                for (int j = 0; j < 4; ++j)
                    acc[i][j] = hfma2u(ad[i], bb[j], acc[i][j]);
        }

        #pragma unroll
        for (int i = 0; i < 4; ++i)
            #pragma unroll
            for (int j = 0; j < 4; ++j) {
                uint32_t a = acc[i][j];
                acc[i][j] = 0u;
                float2 f = __half22float2(*reinterpret_cast<__half2*>(&a));
                facc[i][2 * j]     += f.x;
                facc[i][2 * j + 1] += f.y;
            }

        if ((g & 7) == 7) {
            const int cbase = ((g >> 3) << 7) + (tx << 3);
            #pragma unroll
            for (int i = 0; i < 4; ++i) {
                #pragma unroll
                for (int j = 0; j < 8; ++j) {
                    float sc = fmaf(-2.f, facc[i][j], se2[cbase + j]);
                    facc[i][j] = 0.f;
                    int c = cbase + j;
                    if (sc < bv[i]) {
                        b3[i] = b2[i]; b2[i] = bv[i]; b2i[i] = bi[i];
                        bv[i] = sc; bi[i] = c;
                    } else if (sc < b2[i]) {
                        b3[i] = b2[i]; b2[i] = sc; b2i[i] = c;
                    } else if (sc < b3[i]) {
                        b3[i] = sc;
                    }
                }
            }
        }
    }

    // ---- merge top-3 over the 16 tx lanes sharing each pixel group ----
    #pragma unroll
    for (int o = 1; o <= 8; o <<= 1) {
        #pragma unroll
        for (int i = 0; i < 4; ++i) {
            float o1 = __shfl_xor_sync(0xFFFFFFFFu, bv[i],  o);
            float o2 = __shfl_xor_sync(0xFFFFFFFFu, b2[i],  o);
            float o3 = __shfl_xor_sync(0xFFFFFFFFu, b3[i],  o);
            int  oi1 = __shfl_xor_sync(0xFFFFFFFFu, bi[i],  o);
            int  oi2 = __shfl_xor_sync(0xFFFFFFFFu, b2i[i], o);
            if (o1 < bv[i] || (o1 == bv[i] && oi1 < bi[i])) {
                // other's best is new top1
                if (bv[i] < o2 || (bv[i] == o2 && bi[i] < oi2)) {
                    b3[i]  = fminf(b2[i], o2);
                    b2[i]  = bv[i]; b2i[i] = bi[i];
                } else {
                    b3[i]  = fminf(bv[i], o3);
                    b2[i]  = o2; b2i[i] = oi2;
                }
                bv[i] = o1; bi[i] = oi1;
            } else {
                if (o1 < b2[i] || (o1 == b2[i] && oi1 < b2i[i])) {
                    b3[i]  = fminf(b2[i], o2);
                    b2[i]  = o1; b2i[i] = oi1;
                } else {
                    b3[i]  = fminf(b3[i], o1);
                }
            }
        }
    }
    if (tx == 0) {
        #pragma unroll
        for (int i = 0; i < 4; ++i) {
            int prow = pix0 + (ty << 2) + i;
            g_idx[prow] = bi[i];
            if (b3[i] - bv[i] < MARGIN) {
                int pos = atomicAdd(&g_nB, 1);
                if (pos < FLAGCAPB) g_flagB[pos] = prow;
            } else if (b2[i] - bv[i] < MARGIN) {
                int pos = atomicAdd(&g_nA, 1);
                if (pos < FLAGCAPA) {
                    g_flagA[pos] = prow;
                    g_candA[pos] = make_int2(bi[i], b2i[i]);
                }
            }
        }
    }
}

// ============================================================
// K5a: exact fp32 rescore of the TWO coarse candidates (flag A)
// ============================================================
__global__ __launch_bounds__(256) void k_fixA(const float* __restrict__ z,
                                              const float* __restrict__ emb) {
    const int w = threadIdx.x >> 5, lane = threadIdx.x & 31;
    int n = g_nA; if (n > FLAGCAPA) n = FLAGCAPA;
    for (int f = blockIdx.x * 8 + w; f < n; f += gridDim.x * 8) {
        int pix = g_flagA[f];
        int2 cd = g_candA[f];
        const float* zb = z + (((size_t)(pix >> 12)) << 20) + (pix & 4095);
        float xr[8];
        #pragma unroll
        for (int j = 0; j < 8; ++j) xr[j] = zb[(size_t)(lane * 8 + j) * HW];

        const float4* e0 = reinterpret_cast<const float4*>(emb + (size_t)cd.x * EDIM) + lane * 2;
        const float4* e1 = reinterpret_cast<const float4*>(emb + (size_t)cd.y * EDIM) + lane * 2;
        float4 a0 = e0[0], a1 = e0[1];
        float4 c0 = e1[0], c1 = e1[1];
        float s0 = xr[0] * a0.x, s1 = xr[0] * c0.x;
        s0 = fmaf(xr[1], a0.y, s0); s1 = fmaf(xr[1], c0.y, s1);
        s0 = fmaf(xr[2], a0.z, s0); s1 = fmaf(xr[2], c0.z, s1);
        s0 = fmaf(xr[3], a0.w, s0); s1 = fmaf(xr[3], c0.w, s1);
        s0 = fmaf(xr[4], a1.x, s0); s1 = fmaf(xr[4], c1.x, s1);
        s0 = fmaf(xr[5], a1.y, s0); s1 = fmaf(xr[5], c1.y, s1);
        s0 = fmaf(xr[6], a1.z, s0); s1 = fmaf(xr[6], c1.z, s1);
        s0 = fmaf(xr[7], a1.w, s0); s1 = fmaf(xr[7], c1.w, s1);
        #pragma unroll
        for (int o = 16; o; o >>= 1) {
            s0 += __shfl_xor_sync(0xFFFFFFFFu, s0, o);
            s1 += __shfl_xor_sync(0xFFFFFFFFu, s1, o);
        }
        if (lane == 0) {
            float sc0 = g_e2[cd.x] - 2.f * s0;
            float sc1 = g_e2[cd.y] - 2.f * s1;
            int win = (sc1 < sc0 || (sc1 == sc0 && cd.y < cd.x)) ? cd.y : cd.x;
            g_idx[pix] = win;
        }
        __syncwarp();
    }
}

// ============================================================
// K5b: full exact rescan for 3-way-tie pixels (flag B, rare)
// ============================================================
__global__ __launch_bounds__(256) void k_fixB(const float* __restrict__ z,
                                              const float* __restrict__ emb) {
    const int w = threadIdx.x >> 5, lane = threadIdx.x & 31;
    int n = g_nB; if (n > FLAGCAPB) n = FLAGCAPB;
    for (int f = blockIdx.x * 8 + w; f < n; f += gridDim.x * 8) {
        int pix = g_flagB[f];
        const float* zb = z + (((size_t)(pix >> 12)) << 20) + (pix & 4095);
        float xr[8];
        #pragma unroll
        for (int j = 0; j < 8; ++j) xr[j] = zb[(size_t)(lane * 8 + j) * HW];

        float bv = 3.402823466e38f; int bi = 0;
        #pragma unroll 1
        for (int c = 0; c < NEMB; c += 2) {
            const float4* e0 = reinterpret_cast<const float4*>(emb + (size_t)c * EDIM) + lane * 2;
            const float4* e1 = reinterpret_cast<const float4*>(emb + (size_t)(c + 1) * EDIM) + lane * 2;
            float4 a0 = e0[0], a1 = e0[1];
            float4 c0 = e1[0], c1 = e1[1];
            float s0 = xr[0] * a0.x, s1 = xr[0] * c0.x;
            s0 = fmaf(xr[1], a0.y, s0); s1 = fmaf(xr[1], c0.y, s1);
            s0 = fmaf(xr[2], a0.z, s0); s1 = fmaf(xr[2], c0.z, s1);
            s0 = fmaf(xr[3], a0.w, s0); s1 = fmaf(xr[3], c0.w, s1);
            s0 = fmaf(xr[4], a1.x, s0); s1 = fmaf(xr[4], c1.x, s1);
            s0 = fmaf(xr[5], a1.y, s0); s1 = fmaf(xr[5], c1.y, s1);
            s0 = fmaf(xr[6], a1.z, s0); s1 = fmaf(xr[6], c1.z, s1);
            s0 = fmaf(xr[7], a1.w, s0); s1 = fmaf(xr[7], c1.w, s1);
            #pragma unroll
            for (int o = 16; o; o >>= 1) {
                s0 += __shfl_xor_sync(0xFFFFFFFFu, s0, o);
                s1 += __shfl_xor_sync(0xFFFFFFFFu, s1, o);
            }
            float sc0 = g_e2[c]     - 2.f * s0;
            float sc1 = g_e2[c + 1] - 2.f * s1;
            if (sc0 < bv) { bv = sc0; bi = c; }
            if (sc1 < bv) { bv = sc1; bi = c + 1; }
        }
        if (lane == 0) g_idx[pix] = bi;
        __syncwarp();
    }
}

// ============================================================
// K6: gather z_q, write z_q_st = z_e + (z_q - z_e), loss partials
// ============================================================
__global__ __launch_bounds__(256)
void k_gather(const float* __restrict__ z, const float* __restrict__ emb,
              float* __restrict__ out) {
    __shared__ float sE[32 * 260];
    __shared__ float swarp[8];
    const int t = threadIdx.x;
    const int pix0 = blockIdx.x << 5;

    #pragma unroll
    for (int it = 0; it < 8; ++it) {
        int slot = t + (it << 8);
        int p = slot >> 6, c4 = slot & 63;
        int idx = g_idx[pix0 + p];
        float4 v = *reinterpret_cast<const float4*>(emb + (size_t)idx * EDIM + (c4 << 2));
        *reinterpret_cast<float4*>(&sE[p * 260 + (c4 << 2)]) = v;
    }
    __syncthreads();

    const float* zb = z   + (((size_t)(pix0 >> 12)) << 20) + (pix0 & 4095);
    float*       ob = out + (((size_t)(pix0 >> 12)) << 20) + (pix0 & 4095);

    float lsum = 0.f;
    #pragma unroll
    for (int it = 0; it < 8; ++it) {
        int slot = t + (it << 8);
        int hw = slot & 31, c4 = slot >> 5;
        float4 e = *reinterpret_cast<const float4*>(&sE[hw * 260 + (c4 << 2)]);
        float ev[4] = {e.x, e.y, e.z, e.w};
        #pragma unroll
        for (int j = 0; j < 4; ++j) {
            size_t gg = (size_t)((c4 << 2) + j) * HW + hw;
            float ze = zb[gg];
            float d = ev[j] - ze;
            ob[gg] = ze + d;
            lsum += d * d;
        }
    }
    #pragma unroll
    for (int o = 16; o; o >>= 1) lsum += __shfl_xor_sync(0xFFFFFFFFu, lsum, o);
    if ((t & 31) == 0) swarp[t >> 5] = lsum;
    __syncthreads();
    if (t == 0) {
        double s = 0.0;
        #pragma unroll
        for (int w = 0; w < 8; ++w) s += (double)swarp[w];
        g_part[blockIdx.x] = s;
    }
}

// ============================================================
// K7: loss finalize
// ============================================================
__global__ void k_loss(float* __restrict__ out, int out_size) {
    __shared__ double sd[256];
    int t = threadIdx.x;
    double s = 0.0;
    for (int i = t; i < 2048; i += 256) s += g_part[i];
    sd[t] = s;
    __syncthreads();
    for (int o = 128; o; o >>= 1) {
        if (t < o) sd[t] += sd[t + o];
        __syncthreads();
    }
    if (t == 0 && out_size > NC)
        out[NC] = (float)(0.25 * sd[0] / (double)NC);
}

// ============================================================
extern "C" void kernel_launch(void* const* d_in, const int* in_sizes, int n_in,
                              void* d_out, int out_size) {
    const float* z   = (const float*)d_in[0];
    const float* emb = (const float*)d_in[1];
    float* out = (float*)d_out;

    cudaFuncSetAttribute(k_argmin_hf, cudaFuncAttributeMaxDynamicSharedMemorySize, SM_TOT);

    k_e2     <<<128, 256>>>(emb);
    {
        dim3 grid(32, 8);
        k_bt2<<<grid, 256>>>(emb);
    }
    k_prep_x   <<<2048, 256>>>(z);
    k_argmin_hf<<<1024, 256, SM_TOT>>>();
    k_fixA     <<<512,  256>>>(z, emb);
    k_fixB     <<<128,  256>>>(z, emb);
    k_gather   <<<2048, 256>>>(z, emb, out);
    k_loss     <<<1,    256>>>(out, out_size);
}